// round 6
// baseline (speedup 1.0000x reference)
#include <cuda_runtime.h>
#include <math.h>
#include <stdint.h>

#define BSZ 8
#define NB  8
#define MM  512
#define DD  128
#define NN  1024
#define NBK 64
#define NEGV (-1e30f)

#define OFF_YEM 0
#define OFF_DEM 8388608
#define OFF_K   16777216
#define OFF_V   20971520
#define OFF_S   25165824
#define OFF_AGE 25198592

// ---------------- scratch -----------------------------------------------------
__device__ float g_y[NBK * NN * DD];
__device__ float g_attn[NBK * NN * MM];    // UNNORMALIZED exp
__device__ float g_route[NBK * NN * MM];   // UNNORMALIZED exp
__device__ float g_wnorm[BSZ * NN * DD];
__device__ float g_surp[BSZ * NN];
__device__ float g_nov[NBK * NN];
__device__ float g_rsA[NBK * NN];
__device__ float g_rsR[NBK * NN];
__device__ float g_updK[NBK * MM * DD];
__device__ float g_updV[NBK * MM * DD];
__device__ float g_WnS[NBK * NN * DD];
__device__ float g_WcS[NBK * NN * DD];
__device__ float g_swrP[4 * NBK * MM];
__device__ float g_Khi[NBK * MM * DD];     // tf32-hi of em_K, same layout
__device__ float g_Klo[NBK * MM * DD];     // residual lo

// ---------------- helpers -----------------------------------------------------
__device__ __forceinline__ void fma2(float2 &d, float2 a, float2 b) {
    asm("fma.rn.f32x2 %0, %1, %2, %0;"
        : "+l"(*reinterpret_cast<unsigned long long *>(&d))
        : "l"(*reinterpret_cast<unsigned long long *>(&a)),
          "l"(*reinterpret_cast<unsigned long long *>(&b)));
}
__device__ __forceinline__ float softplusf(float x) {
    return (x > 20.f) ? x : log1pf(expf(x));
}
__device__ __forceinline__ float sigmoidf(float x) {
    return 1.f / (1.f + __expf(-x));
}
__device__ __forceinline__ void tf32_split(float x, float &hi, float &lo) {
    uint32_t h;
    asm("cvt.rna.tf32.f32 %0, %1;" : "=r"(h) : "f"(x));
    hi = __uint_as_float(h);
    lo = x - hi;
}
// m16n8k8 tf32 mma (legacy tensor path; compiles on plain compute_103)
__device__ __forceinline__ void mma1688(float d[4], const uint32_t a[4],
                                        uint32_t b0, uint32_t b1) {
    asm volatile(
        "mma.sync.aligned.m16n8k8.row.col.f32.tf32.tf32.f32 "
        "{%0,%1,%2,%3}, {%4,%5,%6,%7}, {%8,%9}, {%0,%1,%2,%3};"
        : "+f"(d[0]), "+f"(d[1]), "+f"(d[2]), "+f"(d[3])
        : "r"(a[0]), "r"(a[1]), "r"(a[2]), "r"(a[3]), "r"(b0), "r"(b1));
}

// ---------------- em_K tf32 hi/lo split (same layout as emK) -------------------
__global__ void gen_khilo_kernel(const float *__restrict__ emK) {
    int idx = blockIdx.x * 256 + threadIdx.x;      // 1,048,576 float4
    float4 x = reinterpret_cast<const float4 *>(emK)[idx];
    float4 hi, lo;
    tf32_split(x.x, hi.x, lo.x); tf32_split(x.y, hi.y, lo.y);
    tf32_split(x.z, hi.z, lo.z); tf32_split(x.w, hi.w, lo.w);
    reinterpret_cast<float4 *>(g_Khi)[idx] = hi;
    reinterpret_cast<float4 *>(g_Klo)[idx] = lo;
}

// ---------------- y init --------------------------------------------------------
__global__ void init_y_kernel(const float *__restrict__ seed) {
    int i = blockIdx.x * 256 + threadIdx.x;
    int bk = i >> 15;
    int rem = i & 32767;
    int b = bk >> 3;
    reinterpret_cast<float4 *>(g_y)[i] =
        reinterpret_cast<const float4 *>(seed)[b * 32768 + rem];
}

// ---------------- w_norm + surprise magnitude ------------------------------------
__global__ void wnorm_kernel(const float *__restrict__ wc,
                             const float *__restrict__ sp) {
    int row = blockIdx.x;
    int tid = threadIdx.x;
    float w = wc[row * DD + tid];
    float s = sp[row * DD + tid];
    float a = w * w, bb = s * s;
#pragma unroll
    for (int o = 16; o; o >>= 1) {
        a  += __shfl_xor_sync(0xffffffffu, a, o);
        bb += __shfl_xor_sync(0xffffffffu, bb, o);
    }
    __shared__ float ra[4], rb[4];
    if ((tid & 31) == 0) { ra[tid >> 5] = a; rb[tid >> 5] = bb; }
    __syncthreads();
    float na = ra[0] + ra[1] + ra[2] + ra[3];
    float nb = rb[0] + rb[1] + rb[2] + rb[3];
    g_wnorm[row * DD + tid] = w / fmaxf(sqrtf(na), 1e-12f);
    if (tid == 0) g_surp[row] = sqrtf(nb);
}

// ---------------- scores via mma.sync tf32x3 --------------------------------------
// block: 64n x 512m, 512 threads = 16 warps (2 n-rows x 8 m-cols),
// warp tile 32n x 64m. smem float offsets:
#define SC_KHI  0
#define SC_KLO  18432
#define SC_YHI  36864
#define SC_YLO  39168
#define SC_RED  41472
#define SC_SSV  41984
#define SC_FLOATS 42496
#define SC_BYTES (SC_FLOATS * 4)

template <int MODE>
__global__ __launch_bounds__(512) void scores_mma_kernel(
    const float *__restrict__ emS,
    const float *__restrict__ rtau, const float *__restrict__ rtauw) {
    extern __shared__ float sm[];
    float *KHI = sm + SC_KHI, *KLO = sm + SC_KLO;
    float *YHI = sm + SC_YHI, *YLO = sm + SC_YLO;
    float *RED = sm + SC_RED, *SSV = sm + SC_SSV;

    int bk = blockIdx.y, b = bk >> 3, k = bk & 7;
    int n0 = blockIdx.x * 64;
    int tid = threadIdx.x, w = tid >> 5, lane = tid & 31;
    int wr = w >> 3, wc = w & 7;
    int g = lane >> 2, tig = lane & 3;

    const float *Yb = (MODE == 0) ? (g_y + (size_t)bk * NN * DD)
                                  : (g_wnorm + (size_t)b * NN * DD);
    const float *KHIg = g_Khi + (size_t)bk * MM * DD;
    const float *KLOg = g_Klo + (size_t)bk * MM * DD;

    float d[2][8][4];
#pragma unroll
    for (int nt = 0; nt < 2; nt++)
#pragma unroll
        for (int mt = 0; mt < 8; mt++)
#pragma unroll
            for (int c = 0; c < 4; c++) d[nt][mt][c] = 0.f;

    for (int kc = 0; kc < 4; kc++) {
#pragma unroll
        for (int i = 0; i < 8; i++) {       // K chunk: 512 rows x 32 floats
            int f = tid + i * 512;
            int m = f >> 3, q = f & 7;
            *reinterpret_cast<float4 *>(&KHI[m * 36 + q * 4]) =
                *reinterpret_cast<const float4 *>(&KHIg[m * DD + kc * 32 + q * 4]);
            *reinterpret_cast<float4 *>(&KLO[m * 36 + q * 4]) =
                *reinterpret_cast<const float4 *>(&KLOg[m * DD + kc * 32 + q * 4]);
        }
        {   // Y chunk: 64 rows x 32 floats, split
            int row = tid >> 3, q = tid & 7;
            float4 x = *reinterpret_cast<const float4 *>(
                &Yb[(size_t)(n0 + row) * DD + kc * 32 + q * 4]);
            float4 hi, lo;
            tf32_split(x.x, hi.x, lo.x); tf32_split(x.y, hi.y, lo.y);
            tf32_split(x.z, hi.z, lo.z); tf32_split(x.w, hi.w, lo.w);
            *reinterpret_cast<float4 *>(&YHI[row * 36 + q * 4]) = hi;
            *reinterpret_cast<float4 *>(&YLO[row * 36 + q * 4]) = lo;
        }
        __syncthreads();
#pragma unroll
        for (int ks = 0; ks < 4; ks++) {
            int k0 = ks * 8;
            uint32_t ahi[2][4], alo[2][4];
#pragma unroll
            for (int nt = 0; nt < 2; nt++) {
                int base = (wr * 32 + nt * 16 + g) * 36 + k0 + tig;
                ahi[nt][0] = __float_as_uint(YHI[base]);
                ahi[nt][1] = __float_as_uint(YHI[base + 8 * 36]);
                ahi[nt][2] = __float_as_uint(YHI[base + 4]);
                ahi[nt][3] = __float_as_uint(YHI[base + 8 * 36 + 4]);
                alo[nt][0] = __float_as_uint(YLO[base]);
                alo[nt][1] = __float_as_uint(YLO[base + 8 * 36]);
                alo[nt][2] = __float_as_uint(YLO[base + 4]);
                alo[nt][3] = __float_as_uint(YLO[base + 8 * 36 + 4]);
            }
#pragma unroll
            for (int mt = 0; mt < 8; mt++) {
                int bb = (wc * 64 + mt * 8 + g) * 36 + k0 + tig;
                uint32_t bh0 = __float_as_uint(KHI[bb]);
                uint32_t bh1 = __float_as_uint(KHI[bb + 4]);
                uint32_t bl0 = __float_as_uint(KLO[bb]);
                uint32_t bl1 = __float_as_uint(KLO[bb + 4]);
#pragma unroll
                for (int nt = 0; nt < 2; nt++) {
                    mma1688(d[nt][mt], ahi[nt], bh0, bh1);
                    mma1688(d[nt][mt], ahi[nt], bl0, bl1);
                    mma1688(d[nt][mt], alo[nt], bh0, bh1);
                }
            }
        }
        __syncthreads();
    }

    // ---- epilogue: masked two-temperature exp + row sums --------------------
    float sv = emS[bk * MM + tid];
    SSV[tid] = sv;
    int hasAny = __syncthreads_or(sv > 0.f);

    bool act[8][2];
#pragma unroll
    for (int mt = 0; mt < 8; mt++) {
        int c = wc * 64 + mt * 8 + tig * 2;
        act[mt][0] = SSV[c] > 0.f;
        act[mt][1] = SSV[c + 1] > 0.f;
    }
    float inv_tau  = 1.f / (softplusf(rtau[k]) + 0.1f);
    float inv_tauw = 1.f / (softplusf(rtauw[k]) + 0.1f);

    // row maxima (4 rows per thread-quad: nt x {lo,hi})
#pragma unroll
    for (int nt = 0; nt < 2; nt++) {
        float m0 = NEGV, m1 = NEGV;
#pragma unroll
        for (int mt = 0; mt < 8; mt++) {
            if (act[mt][0]) { m0 = fmaxf(m0, d[nt][mt][0]); m1 = fmaxf(m1, d[nt][mt][2]); }
            if (act[mt][1]) { m0 = fmaxf(m0, d[nt][mt][1]); m1 = fmaxf(m1, d[nt][mt][3]); }
        }
#pragma unroll
        for (int o = 1; o <= 2; o <<= 1) {
            m0 = fmaxf(m0, __shfl_xor_sync(0xffffffffu, m0, o));
            m1 = fmaxf(m1, __shfl_xor_sync(0xffffffffu, m1, o));
        }
        if (tig == 0) {
            RED[(wr * 32 + nt * 16 + g) * 8 + wc] = m0;
            RED[(wr * 32 + nt * 16 + g + 8) * 8 + wc] = m1;
        }
    }
    __syncthreads();
    float gmx[2][2];
#pragma unroll
    for (int nt = 0; nt < 2; nt++)
#pragma unroll
        for (int h = 0; h < 2; h++) {
            int r = wr * 32 + nt * 16 + g + h * 8;
            float m = RED[r * 8];
#pragma unroll
            for (int i = 1; i < 8; i++) m = fmaxf(m, RED[r * 8 + i]);
            gmx[nt][h] = m;
        }
    __syncthreads();

    int np = (MODE == 1) ? 2 : 1;
    for (int p = 0; p < np; p++) {
        float sc = (p == 0) ? inv_tau : inv_tauw;
        float *op = (p == 0) ? g_attn : g_route;
        float rs[2][2] = {{0.f, 0.f}, {0.f, 0.f}};
#pragma unroll
        for (int nt = 0; nt < 2; nt++) {
            int rlo = n0 + wr * 32 + nt * 16 + g;
            size_t blo = ((size_t)bk * NN + rlo) * MM + wc * 64 + tig * 2;
            size_t bhi = blo + 8 * MM;
#pragma unroll
            for (int mt = 0; mt < 8; mt++) {
                float e00, e01, e10, e11;
                if (!hasAny) { e00 = e01 = e10 = e11 = 1.f; }
                else {
                    e00 = act[mt][0] ? __expf((d[nt][mt][0] - gmx[nt][0]) * sc) : 0.f;
                    e01 = act[mt][1] ? __expf((d[nt][mt][1] - gmx[nt][0]) * sc) : 0.f;
                    e10 = act[mt][0] ? __expf((d[nt][mt][2] - gmx[nt][1]) * sc) : 0.f;
                    e11 = act[mt][1] ? __expf((d[nt][mt][3] - gmx[nt][1]) * sc) : 0.f;
                }
                rs[nt][0] += e00 + e01;
                rs[nt][1] += e10 + e11;
                *reinterpret_cast<float2 *>(&op[blo + mt * 8]) = make_float2(e00, e01);
                *reinterpret_cast<float2 *>(&op[bhi + mt * 8]) = make_float2(e10, e11);
            }
#pragma unroll
            for (int o = 1; o <= 2; o <<= 1) {
                rs[nt][0] += __shfl_xor_sync(0xffffffffu, rs[nt][0], o);
                rs[nt][1] += __shfl_xor_sync(0xffffffffu, rs[nt][1], o);
            }
            if (tig == 0) {
                RED[(wr * 32 + nt * 16 + g) * 8 + wc] = rs[nt][0];
                RED[(wr * 32 + nt * 16 + g + 8) * 8 + wc] = rs[nt][1];
            }
        }
        __syncthreads();
        if (tid < 64) {
            float t = 0.f;
#pragma unroll
            for (int i = 0; i < 8; i++) t += RED[tid * 8 + i];
            size_t nidx = (size_t)bk * NN + n0 + tid;
            if (p == 0) g_rsA[nidx] = hasAny ? (1.f / t) : 0.f;
            else        g_rsR[nidx] = 1.f / t;
        }
        __syncthreads();
    }
}

// ---------------- A@V GEMM (SIMT) --------------------------------------------------
template <int MODE>
__global__ __launch_bounds__(256, 2) void av_kernel(
    const float *__restrict__ emV, const float *__restrict__ w1,
    const float *__restrict__ w2, const float *__restrict__ gb,
    const float *__restrict__ seed, const float *__restrict__ wcand,
    float *__restrict__ out) {
    __shared__ __align__(16) float AsT[32][132];
    __shared__ __align__(16) float Vs[32][132];
    int bk = blockIdx.y, b = bk >> 3, k = bk & 7;
    int n0 = blockIdx.x * 128;
    int tid = threadIdx.x, wid = tid >> 5, tx = tid & 31;
    const float *Ab = g_attn + (size_t)bk * NN * MM;
    const float *Vb = emV + (size_t)bk * MM * DD;

    float2 acc[16][2];
#pragma unroll
    for (int r = 0; r < 16; r++) {
        acc[r][0] = make_float2(0.f, 0.f);
        acc[r][1] = make_float2(0.f, 0.f);
    }

    for (int m0 = 0; m0 < MM; m0 += 32) {
#pragma unroll
        for (int i = 0; i < 4; i++) {
            int idx = tid + i * 256;
            int row = idx >> 3, q = idx & 7;
            float4 v = *reinterpret_cast<const float4 *>(
                &Ab[(size_t)(n0 + row) * MM + m0 + q * 4]);
            AsT[q * 4 + 0][row] = v.x; AsT[q * 4 + 1][row] = v.y;
            AsT[q * 4 + 2][row] = v.z; AsT[q * 4 + 3][row] = v.w;
        }
#pragma unroll
        for (int i = 0; i < 4; i++) {
            int idx = tid + i * 256;
            int mm = idx >> 5, dq = idx & 31;
            *reinterpret_cast<float4 *>(&Vs[mm][dq * 4]) =
                *reinterpret_cast<const float4 *>(
                    &Vb[(size_t)(m0 + mm) * DD + dq * 4]);
        }
        __syncthreads();
#pragma unroll
        for (int mm = 0; mm < 32; mm++) {
            float4 a0 = *reinterpret_cast<const float4 *>(&AsT[mm][wid * 16]);
            float4 a1 = *reinterpret_cast<const float4 *>(&AsT[mm][wid * 16 + 4]);
            float4 a2 = *reinterpret_cast<const float4 *>(&AsT[mm][wid * 16 + 8]);
            float4 a3 = *reinterpret_cast<const float4 *>(&AsT[mm][wid * 16 + 12]);
            float ar[16] = {a0.x, a0.y, a0.z, a0.w, a1.x, a1.y, a1.z, a1.w,
                            a2.x, a2.y, a2.z, a2.w, a3.x, a3.y, a3.z, a3.w};
            float4 v4 = *reinterpret_cast<const float4 *>(&Vs[mm][tx * 4]);
            float2 vlo = make_float2(v4.x, v4.y);
            float2 vhi = make_float2(v4.z, v4.w);
#pragma unroll
            for (int r = 0; r < 16; r++) {
                fma2(acc[r][0], make_float2(ar[r], ar[r]), vlo);
                fma2(acc[r][1], make_float2(ar[r], ar[r]), vhi);
            }
        }
        __syncthreads();
    }

    int rowbase = n0 + wid * 16;
    int d = tx * 4;

    if (MODE == 0 || MODE == 1) {
        const float4 w1v = *reinterpret_cast<const float4 *>(&w1[k * DD + d]);
        const float4 w2v = *reinterpret_cast<const float4 *>(&w2[k * DD + d]);
        const float4 gbv = *reinterpret_cast<const float4 *>(&gb[k * DD + d]);
#pragma unroll
        for (int r = 0; r < 16; r++) {
            int n = rowbase + r;
            float s = g_rsA[(size_t)bk * NN + n];
            size_t yb = ((size_t)bk * NN + n) * DD + d;
            float4 yo = *reinterpret_cast<const float4 *>(&g_y[yb]);
            float dl0 = s * acc[r][0].x, dl1 = s * acc[r][0].y;
            float dl2 = s * acc[r][1].x, dl3 = s * acc[r][1].y;
            float g0 = sigmoidf(w1v.x * yo.x + w2v.x * dl0 + gbv.x);
            float g1 = sigmoidf(w1v.y * yo.y + w2v.y * dl1 + gbv.y);
            float g2 = sigmoidf(w1v.z * yo.z + w2v.z * dl2 + gbv.z);
            float g3 = sigmoidf(w1v.w * yo.w + w2v.w * dl3 + gbv.w);
            float4 yn = make_float4(yo.x + g0 * dl0, yo.y + g1 * dl1,
                                    yo.z + g2 * dl2, yo.w + g3 * dl3);
            if (MODE == 0) {
                *reinterpret_cast<float4 *>(&g_y[yb]) = yn;
            } else {
                float4 sd = *reinterpret_cast<const float4 *>(
                    &seed[((size_t)b * NN + n) * DD + d]);
                *reinterpret_cast<float4 *>(
                    &out[OFF_YEM + (((size_t)b * NN + n) * NB + k) * DD + d]) =
                    make_float4(yn.x - sd.x, yn.y - sd.y, yn.z - sd.z, yn.w - sd.w);
            }
        }
    } else {
        float psq[16];
#pragma unroll
        for (int r = 0; r < 16; r++) {
            int n = rowbase + r;
            float s = g_rsA[(size_t)bk * NN + n];
            float4 w = *reinterpret_cast<const float4 *>(
                &wcand[((size_t)b * NN + n) * DD + d]);
            float r0 = w.x - s * acc[r][0].x;
            float r1 = w.y - s * acc[r][0].y;
            float r2 = w.z - s * acc[r][1].x;
            float r3 = w.w - s * acc[r][1].y;
            psq[r] = r0 * r0 + r1 * r1 + r2 * r2 + r3 * r3;
        }
#pragma unroll
        for (int r = 0; r < 16; r++)
#pragma unroll
            for (int o = 16; o; o >>= 1)
                psq[r] += __shfl_xor_sync(0xffffffffu, psq[r], o);
#pragma unroll
        for (int r = 0; r < 16; r++) {
            int n = rowbase + r;
            float nv = 0.5f * g_surp[b * NN + n] + 0.5f * sqrtf(psq[r]);
            if (tx == 0) g_nov[bk * NN + n] = nv;
            float rsR = g_rsR[(size_t)bk * NN + n];
            float4 w = *reinterpret_cast<const float4 *>(
                &wcand[((size_t)b * NN + n) * DD + d]);
            float4 wn = *reinterpret_cast<const float4 *>(
                &g_wnorm[((size_t)b * NN + n) * DD + d]);
            float4 dem = make_float4(nv * w.x, nv * w.y, nv * w.z, nv * w.w);
            *reinterpret_cast<float4 *>(
                &out[OFF_DEM + (((size_t)b * NN + n) * NB + k) * DD + d]) = dem;
            size_t so = ((size_t)bk * NN + n) * DD + d;
            *reinterpret_cast<float4 *>(&g_WcS[so]) =
                make_float4(rsR * dem.x, rsR * dem.y, rsR * dem.z, rsR * dem.w);
            float np2 = nv * rsR;
            *reinterpret_cast<float4 *>(&g_WnS[so]) =
                make_float4(np2 * wn.x, np2 * wn.y, np2 * wn.z, np2 * wn.w);
        }
    }
}

// ---------------- swr partial ------------------------------------------------------
__global__ __launch_bounds__(256) void swr_kernel() {
    int bk = blockIdx.x, chunk = blockIdx.y;
    int t = threadIdx.x;
    float2 acc = make_float2(0.f, 0.f);
#pragma unroll 4
    for (int i = 0; i < 256; i++) {
        int n = chunk * 256 + i;
        float novp = g_nov[bk * NN + n] * g_rsR[bk * NN + n];
        float2 e = *reinterpret_cast<const float2 *>(
            &g_route[((size_t)bk * NN + n) * MM + t * 2]);
        acc.x += novp * e.x;
        acc.y += novp * e.y;
    }
    *reinterpret_cast<float2 *>(&g_swrP[(chunk * NBK + bk) * MM + t * 2]) = acc;
}

// ---------------- update_K / update_V pure GEMM -------------------------------------
__global__ __launch_bounds__(256, 2) void updkv_kernel() {
    __shared__ __align__(16) float WRs[32][72];
    __shared__ __align__(16) float WnSs[32][132];
    __shared__ __align__(16) float WcSs[32][132];
    int bk = blockIdx.y;
    int m0 = blockIdx.x * 64;
    int tid = threadIdx.x, wid = tid >> 5, tx = tid & 31;

    float2 aK[8][2], aV[8][2];
#pragma unroll
    for (int r = 0; r < 8; r++) {
        aK[r][0] = make_float2(0.f, 0.f); aK[r][1] = make_float2(0.f, 0.f);
        aV[r][0] = make_float2(0.f, 0.f); aV[r][1] = make_float2(0.f, 0.f);
    }

    for (int n0 = 0; n0 < NN; n0 += 32) {
#pragma unroll
        for (int i = 0; i < 2; i++) {
            int idx = tid + i * 256;
            int nn = idx >> 4, q = idx & 15;
            *reinterpret_cast<float4 *>(&WRs[nn][q * 4]) =
                *reinterpret_cast<const float4 *>(
                    &g_route[((size_t)bk * NN + n0 + nn) * MM + m0 + q * 4]);
        }
#pragma unroll
        for (int i = 0; i < 4; i++) {
            int idx = tid + i * 256;
            int nn = idx >> 5, dq = idx & 31;
            size_t base = ((size_t)bk * NN + n0 + nn) * DD + dq * 4;
            *reinterpret_cast<float4 *>(&WnSs[nn][dq * 4]) =
                *reinterpret_cast<const float4 *>(&g_WnS[base]);
            *reinterpret_cast<float4 *>(&WcSs[nn][dq * 4]) =
                *reinterpret_cast<const float4 *>(&g_WcS[base]);
        }
        __syncthreads();
#pragma unroll
        for (int nn = 0; nn < 32; nn++) {
            float4 e0 = *reinterpret_cast<const float4 *>(&WRs[nn][wid * 8]);
            float4 e1 = *reinterpret_cast<const float4 *>(&WRs[nn][wid * 8 + 4]);
            float er[8] = {e0.x, e0.y, e0.z, e0.w, e1.x, e1.y, e1.z, e1.w};
            float4 wn = *reinterpret_cast<const float4 *>(&WnSs[nn][tx * 4]);
            float4 wc = *reinterpret_cast<const float4 *>(&WcSs[nn][tx * 4]);
            float2 nlo = make_float2(wn.x, wn.y), nhi = make_float2(wn.z, wn.w);
            float2 clo = make_float2(wc.x, wc.y), chi = make_float2(wc.z, wc.w);
#pragma unroll
            for (int r = 0; r < 8; r++) {
                float2 ep = make_float2(er[r], er[r]);
                fma2(aK[r][0], ep, nlo);
                fma2(aK[r][1], ep, nhi);
                fma2(aV[r][0], ep, clo);
                fma2(aV[r][1], ep, chi);
            }
        }
        __syncthreads();
    }
#pragma unroll
    for (int r = 0; r < 8; r++) {
        int m = m0 + wid * 8 + r;
        size_t off = ((size_t)bk * MM + m) * DD + tx * 4;
        *reinterpret_cast<float4 *>(&g_updK[off]) =
            make_float4(aK[r][0].x, aK[r][0].y, aK[r][1].x, aK[r][1].y);
        *reinterpret_cast<float4 *>(&g_updV[off]) =
            make_float4(aV[r][0].x, aV[r][0].y, aV[r][1].x, aV[r][1].y);
    }
}

// ---------------- final ---------------------------------------------------------------
__global__ __launch_bounds__(256) void final_kernel(
    const float *__restrict__ emK, const float *__restrict__ emV,
    const float *__restrict__ emS, const float *__restrict__ emAge,
    const float *__restrict__ gem, float *__restrict__ out) {
    int bk = blockIdx.x, b = bk >> 3, k = bk & 7;
    int tid = threadIdx.x, warp = tid >> 5, lane = tid & 31;
    float ge = gem[b * NB + k];
    const float invN = 1.f / (float)NN;

    for (int m = warp; m < MM; m += 8) {
        float swv = g_swrP[bk * MM + m] + g_swrP[NBK * MM + bk * MM + m]
                  + g_swrP[2 * NBK * MM + bk * MM + m]
                  + g_swrP[3 * NBK * MM + bk * MM + m];
        float denom = fmaxf(swv, 1e-8f);
        float alpha = fminf(ge * swv * invN, 1.f);
        float oma = 1.f - alpha;
        float idn = 1.f / denom;
        size_t off = ((size_t)bk * MM + m) * DD + lane * 4;
        float4 uk = *reinterpret_cast<const float4 *>(&g_updK[off]);
        uk.x *= idn; uk.y *= idn; uk.z *= idn; uk.w *= idn;
        float sq = uk.x * uk.x + uk.y * uk.y + uk.z * uk.z + uk.w * uk.w;
#pragma unroll
        for (int o = 16; o; o >>= 1) sq += __shfl_xor_sync(0xffffffffu, sq, o);
        float inv = 1.f / fmaxf(sqrtf(sq), 1e-12f);
        float ai = alpha * inv;
        float4 ek = *reinterpret_cast<const float4 *>(&emK[off]);
        *reinterpret_cast<float4 *>(&out[OFF_K + off]) =
            make_float4(oma * ek.x + ai * uk.x, oma * ek.y + ai * uk.y,
                        oma * ek.z + ai * uk.z, oma * ek.w + ai * uk.w);
        float4 uv = *reinterpret_cast<const float4 *>(&g_updV[off]);
        uv.x *= idn; uv.y *= idn; uv.z *= idn; uv.w *= idn;
        float4 ev = *reinterpret_cast<const float4 *>(&emV[off]);
        *reinterpret_cast<float4 *>(&out[OFF_V + off]) =
            make_float4(oma * ev.x + alpha * uv.x, oma * ev.y + alpha * uv.y,
                        oma * ev.z + alpha * uv.z, oma * ev.w + alpha * uv.w);
    }

    __shared__ float red[8];
    __shared__ float stot;
    float part = 0.f, sn[2], al[2];
#pragma unroll
    for (int i = 0; i < 2; i++) {
        int m = tid + i * 256;
        float swv = g_swrP[bk * MM + m] + g_swrP[NBK * MM + bk * MM + m]
                  + g_swrP[2 * NBK * MM + bk * MM + m]
                  + g_swrP[3 * NBK * MM + bk * MM + m];
        al[i] = fminf(ge * swv * invN, 1.f);
        float v = emS[bk * MM + m] + al[i];
        v = fminf(fmaxf(v, 0.f), 3.0f);
        sn[i] = v; part += v;
    }
#pragma unroll
    for (int o = 16; o; o >>= 1) part += __shfl_xor_sync(0xffffffffu, part, o);
    if (lane == 0) red[warp] = part;
    __syncthreads();
    if (tid == 0) {
        float t = 0.f;
        for (int i = 0; i < 8; i++) t += red[i];
        stot = t;
    }
    __syncthreads();
    float scale = fminf(1.f, 32.0f / fmaxf(stot, 1e-8f));
#pragma unroll
    for (int i = 0; i < 2; i++) {
        int m = tid + i * 256;
        out[OFF_S + bk * MM + m] = sn[i] * scale;
        out[OFF_AGE + bk * MM + m] = emAge[bk * MM + m] * (1.f - al[i]);
    }
}

// ---------------- launcher --------------------------------------------------------------
extern "C" void kernel_launch(void *const *d_in, const int *in_sizes, int n_in,
                              void *d_out, int out_size) {
    const float *seed     = (const float *)d_in[0];
    const float *wcand    = (const float *)d_in[1];
    const float *surprise = (const float *)d_in[2];
    const float *gem      = (const float *)d_in[3];
    const float *emK      = (const float *)d_in[4];
    const float *emV      = (const float *)d_in[5];
    const float *emS      = (const float *)d_in[6];
    const float *emAge    = (const float *)d_in[7];
    const float *w1       = (const float *)d_in[8];
    const float *w2       = (const float *)d_in[9];
    const float *gb       = (const float *)d_in[10];
    const float *rtau     = (const float *)d_in[11];
    const float *rtauw    = (const float *)d_in[12];
    float *out = (float *)d_out;

    cudaFuncSetAttribute(scores_mma_kernel<0>,
                         cudaFuncAttributeMaxDynamicSharedMemorySize, SC_BYTES);
    cudaFuncSetAttribute(scores_mma_kernel<1>,
                         cudaFuncAttributeMaxDynamicSharedMemorySize, SC_BYTES);

    dim3 gS(16, 64), gB(8, 64), gU(8, 64);

    gen_khilo_kernel<<<4096, 256>>>(emK);
    init_y_kernel<<<8192, 256>>>(seed);
    wnorm_kernel<<<8192, 128>>>(wcand, surprise);

    scores_mma_kernel<0><<<gS, 512, SC_BYTES>>>(emS, rtau, rtauw);
    av_kernel<0><<<gB, 256>>>(emV, w1, w2, gb, seed, wcand, out);
    scores_mma_kernel<0><<<gS, 512, SC_BYTES>>>(emS, rtau, rtauw);
    av_kernel<1><<<gB, 256>>>(emV, w1, w2, gb, seed, wcand, out);

    scores_mma_kernel<1><<<gS, 512, SC_BYTES>>>(emS, rtau, rtauw);
    av_kernel<2><<<gB, 256>>>(emV, w1, w2, gb, seed, wcand, out);

    swr_kernel<<<dim3(64, 4), 256>>>();
    updkv_kernel<<<gU, 256>>>();
    final_kernel<<<64, 256>>>(emK, emV, emS, emAge, gem, out);
}

// round 7
// speedup vs baseline: 1.1220x; 1.1220x over previous
#include <cuda_runtime.h>
#include <math.h>
#include <stdint.h>

#define BSZ 8
#define NB  8
#define MM  512
#define DD  128
#define NN  1024
#define NBK 64
#define NEGV (-1e30f)

#define OFF_YEM 0
#define OFF_DEM 8388608
#define OFF_K   16777216
#define OFF_V   20971520
#define OFF_S   25165824
#define OFF_AGE 25198592

// ---------------- scratch -----------------------------------------------------
__device__ float g_y[NBK * NN * DD];
__device__ float g_attn[NBK * NN * MM];    // UNNORMALIZED exp
__device__ float g_route[NBK * NN * MM];   // UNNORMALIZED exp
__device__ float g_wnorm[BSZ * NN * DD];
__device__ float g_surp[BSZ * NN];
__device__ float g_nov[NBK * NN];
__device__ float g_rsA[NBK * NN];
__device__ float g_rsR[NBK * NN];
__device__ float g_updK[NBK * MM * DD];
__device__ float g_updV[NBK * MM * DD];
__device__ float g_WnS[NBK * NN * DD];
__device__ float g_WcS[NBK * NN * DD];
__device__ float g_swrP[4 * NBK * MM];
__device__ float g_Vt[NBK * DD * MM];      // em_V transposed (bk, d, m)

// ---------------- helpers -----------------------------------------------------
__device__ __forceinline__ void fma2(float2 &d, float2 a, float2 b) {
    asm("fma.rn.f32x2 %0, %1, %2, %0;"
        : "+l"(*reinterpret_cast<unsigned long long *>(&d))
        : "l"(*reinterpret_cast<unsigned long long *>(&a)),
          "l"(*reinterpret_cast<unsigned long long *>(&b)));
}
__device__ __forceinline__ float softplusf(float x) {
    return (x > 20.f) ? x : log1pf(expf(x));
}
__device__ __forceinline__ float sigmoidf(float x) {
    return 1.f / (1.f + __expf(-x));
}
__device__ __forceinline__ void tf32_split(float x, float &hi, float &lo) {
    uint32_t h;
    asm("cvt.rna.tf32.f32 %0, %1;" : "=r"(h) : "f"(x));
    hi = __uint_as_float(h);
    lo = x - hi;
}
__device__ __forceinline__ uint32_t smem_u32(const void *p) {
    uint32_t a;
    asm("{ .reg .u64 t; cvta.to.shared.u64 t, %1; cvt.u32.u64 %0, t; }"
        : "=r"(a) : "l"(p));
    return a;
}
__device__ __forceinline__ void cp_async16(uint32_t saddr, const void *gaddr) {
    asm volatile("cp.async.cg.shared.global [%0], [%1], 16;"
                 :: "r"(saddr), "l"(gaddr) : "memory");
}
#define CP_COMMIT() asm volatile("cp.async.commit_group;" ::: "memory")
#define CP_WAIT(n)  asm volatile("cp.async.wait_group %0;" :: "n"(n) : "memory")

__device__ __forceinline__ void mma1688(float d[4], const uint32_t a[4],
                                        uint32_t b0, uint32_t b1) {
    asm volatile(
        "mma.sync.aligned.m16n8k8.row.col.f32.tf32.tf32.f32 "
        "{%0,%1,%2,%3}, {%4,%5,%6,%7}, {%8,%9}, {%0,%1,%2,%3};"
        : "+f"(d[0]), "+f"(d[1]), "+f"(d[2]), "+f"(d[3])
        : "r"(a[0]), "r"(a[1]), "r"(a[2]), "r"(a[3]), "r"(b0), "r"(b1));
}

// ---------------- V transpose: g_Vt[bk][d][m] = emV[bk][m][d] -------------------
__global__ void transpose_v_kernel(const float *__restrict__ emV) {
    __shared__ float t[32][33];
    int bk = blockIdx.z;
    int m0 = blockIdx.x * 32, d0 = blockIdx.y * 32;
    int x = threadIdx.x, y0 = threadIdx.y;
#pragma unroll
    for (int yy = 0; yy < 32; yy += 8)
        t[y0 + yy][x] = emV[((size_t)bk * MM + m0 + y0 + yy) * DD + d0 + x];
    __syncthreads();
#pragma unroll
    for (int yy = 0; yy < 32; yy += 8)
        g_Vt[((size_t)bk * DD + d0 + y0 + yy) * MM + m0 + x] = t[x][y0 + yy];
}

// ---------------- y init --------------------------------------------------------
__global__ void init_y_kernel(const float *__restrict__ seed) {
    int i = blockIdx.x * 256 + threadIdx.x;
    int bk = i >> 15;
    int rem = i & 32767;
    int b = bk >> 3;
    reinterpret_cast<float4 *>(g_y)[i] =
        reinterpret_cast<const float4 *>(seed)[b * 32768 + rem];
}

// ---------------- w_norm + surprise magnitude ------------------------------------
__global__ void wnorm_kernel(const float *__restrict__ wc,
                             const float *__restrict__ sp) {
    int row = blockIdx.x;
    int tid = threadIdx.x;
    float w = wc[row * DD + tid];
    float s = sp[row * DD + tid];
    float a = w * w, bb = s * s;
#pragma unroll
    for (int o = 16; o; o >>= 1) {
        a  += __shfl_xor_sync(0xffffffffu, a, o);
        bb += __shfl_xor_sync(0xffffffffu, bb, o);
    }
    __shared__ float ra[4], rb[4];
    if ((tid & 31) == 0) { ra[tid >> 5] = a; rb[tid >> 5] = bb; }
    __syncthreads();
    float na = ra[0] + ra[1] + ra[2] + ra[3];
    float nb = rb[0] + rb[1] + rb[2] + rb[3];
    g_wnorm[row * DD + tid] = w / fmaxf(sqrtf(na), 1e-12f);
    if (tid == 0) g_surp[row] = sqrtf(nb);
}

// ---------------- scores via mma.sync tf32x3, cp.async pipelined ------------------
// block 64n x 512m, 512 thr, 16 warps (wr 2 x wc 8); warp tile 32n x 64m.
// smem: KS 2x(512x36), YS 2x(64x36), RED 512, SSV 512  (floats)
#define SC_YOFF  36864
#define SC_REDO  41472
#define SC_SSVO  41984
#define SC_FLOATS 42496
#define SC_BYTES (SC_FLOATS * 4)

template <int MODE>
__global__ __launch_bounds__(512) void scores_mma_kernel(
    const float *__restrict__ emK, const float *__restrict__ emS,
    const float *__restrict__ rtau, const float *__restrict__ rtauw) {
    extern __shared__ __align__(16) float sm[];
    float *RED = sm + SC_REDO;
    float *SSV = sm + SC_SSVO;
    uint32_t sb = smem_u32(sm);

    int bk = blockIdx.y, b = bk >> 3, k = bk & 7;
    int n0 = blockIdx.x * 64;
    int tid = threadIdx.x, w = tid >> 5, lane = tid & 31;
    int wr = w >> 3, wc = w & 7;
    int g = lane >> 2, tig = lane & 3;

    const float *Yb = (MODE == 0) ? (g_y + (size_t)bk * NN * DD)
                                  : (g_wnorm + (size_t)b * NN * DD);
    const float *Kb = emK + (size_t)bk * MM * DD;

    float d[2][8][4];
#pragma unroll
    for (int nt = 0; nt < 2; nt++)
#pragma unroll
        for (int mt = 0; mt < 8; mt++)
#pragma unroll
            for (int c = 0; c < 4; c++) d[nt][mt][c] = 0.f;

    auto prefetch = [&](int kc, int st) {
#pragma unroll
        for (int i = 0; i < 8; i++) {       // K: 512 rows x 32 fl
            int f = tid + i * 512;
            int m = f >> 3, q = f & 7;
            cp_async16(sb + (st * 18432 + m * 36 + q * 4) * 4,
                       Kb + (size_t)m * DD + kc * 32 + q * 4);
        }
        {                                   // Y: 64 rows x 32 fl (512 f4 exactly)
            int row = tid >> 3, q = tid & 7;
            cp_async16(sb + (SC_YOFF + st * 2304 + row * 36 + q * 4) * 4,
                       Yb + (size_t)(n0 + row) * DD + kc * 32 + q * 4);
        }
        CP_COMMIT();
    };

    prefetch(0, 0);
    for (int kc = 0; kc < 4; kc++) {
        int st = kc & 1;
        if (kc < 3) { prefetch(kc + 1, st ^ 1); CP_WAIT(1); }
        else        { CP_WAIT(0); }
        __syncthreads();
        const float *Kst = sm + st * 18432;
        const float *Yst = sm + SC_YOFF + st * 2304;
#pragma unroll
        for (int ks = 0; ks < 4; ks++) {
            int k0 = ks * 8;
            uint32_t ahi[2][4], alo[2][4];
#pragma unroll
            for (int nt = 0; nt < 2; nt++) {
                int base = (wr * 32 + nt * 16 + g) * 36 + k0 + tig;
                float r0 = Yst[base], r1 = Yst[base + 8 * 36];
                float r2 = Yst[base + 4], r3 = Yst[base + 8 * 36 + 4];
                float h, l;
                tf32_split(r0, h, l); ahi[nt][0] = __float_as_uint(h); alo[nt][0] = __float_as_uint(l);
                tf32_split(r1, h, l); ahi[nt][1] = __float_as_uint(h); alo[nt][1] = __float_as_uint(l);
                tf32_split(r2, h, l); ahi[nt][2] = __float_as_uint(h); alo[nt][2] = __float_as_uint(l);
                tf32_split(r3, h, l); ahi[nt][3] = __float_as_uint(h); alo[nt][3] = __float_as_uint(l);
            }
#pragma unroll
            for (int mt = 0; mt < 8; mt++) {
                int bb = (wc * 64 + mt * 8 + g) * 36 + k0 + tig;
                float q0 = Kst[bb], q1 = Kst[bb + 4];
                float h0, l0, h1, l1;
                tf32_split(q0, h0, l0);
                tf32_split(q1, h1, l1);
                uint32_t bh0 = __float_as_uint(h0), bl0 = __float_as_uint(l0);
                uint32_t bh1 = __float_as_uint(h1), bl1 = __float_as_uint(l1);
#pragma unroll
                for (int nt = 0; nt < 2; nt++) {
                    mma1688(d[nt][mt], ahi[nt], bh0, bh1);
                    mma1688(d[nt][mt], ahi[nt], bl0, bl1);
                    mma1688(d[nt][mt], alo[nt], bh0, bh1);
                }
            }
        }
        __syncthreads();
    }

    // ---- epilogue (layout identical to R6, which verified) -------------------
    float sv = emS[bk * MM + tid];
    SSV[tid] = sv;
    int hasAny = __syncthreads_or(sv > 0.f);

    bool act[8][2];
#pragma unroll
    for (int mt = 0; mt < 8; mt++) {
        int c = wc * 64 + mt * 8 + tig * 2;
        act[mt][0] = SSV[c] > 0.f;
        act[mt][1] = SSV[c + 1] > 0.f;
    }
    float inv_tau  = 1.f / (softplusf(rtau[k]) + 0.1f);
    float inv_tauw = 1.f / (softplusf(rtauw[k]) + 0.1f);

#pragma unroll
    for (int nt = 0; nt < 2; nt++) {
        float m0 = NEGV, m1 = NEGV;
#pragma unroll
        for (int mt = 0; mt < 8; mt++) {
            if (act[mt][0]) { m0 = fmaxf(m0, d[nt][mt][0]); m1 = fmaxf(m1, d[nt][mt][2]); }
            if (act[mt][1]) { m0 = fmaxf(m0, d[nt][mt][1]); m1 = fmaxf(m1, d[nt][mt][3]); }
        }
#pragma unroll
        for (int o = 1; o <= 2; o <<= 1) {
            m0 = fmaxf(m0, __shfl_xor_sync(0xffffffffu, m0, o));
            m1 = fmaxf(m1, __shfl_xor_sync(0xffffffffu, m1, o));
        }
        if (tig == 0) {
            RED[(wr * 32 + nt * 16 + g) * 8 + wc] = m0;
            RED[(wr * 32 + nt * 16 + g + 8) * 8 + wc] = m1;
        }
    }
    __syncthreads();
    float gmx[2][2];
#pragma unroll
    for (int nt = 0; nt < 2; nt++)
#pragma unroll
        for (int h = 0; h < 2; h++) {
            int r = wr * 32 + nt * 16 + g + h * 8;
            float m = RED[r * 8];
#pragma unroll
            for (int i = 1; i < 8; i++) m = fmaxf(m, RED[r * 8 + i]);
            gmx[nt][h] = m;
        }
    __syncthreads();

    int np = (MODE == 1) ? 2 : 1;
    for (int p = 0; p < np; p++) {
        float sc = (p == 0) ? inv_tau : inv_tauw;
        float *op = (p == 0) ? g_attn : g_route;
        float rs[2][2] = {{0.f, 0.f}, {0.f, 0.f}};
#pragma unroll
        for (int nt = 0; nt < 2; nt++) {
            int rlo = n0 + wr * 32 + nt * 16 + g;
            size_t blo = ((size_t)bk * NN + rlo) * MM + wc * 64 + tig * 2;
            size_t bhi = blo + 8 * MM;
#pragma unroll
            for (int mt = 0; mt < 8; mt++) {
                float e00, e01, e10, e11;
                if (!hasAny) { e00 = e01 = e10 = e11 = 1.f; }
                else {
                    e00 = act[mt][0] ? __expf((d[nt][mt][0] - gmx[nt][0]) * sc) : 0.f;
                    e01 = act[mt][1] ? __expf((d[nt][mt][1] - gmx[nt][0]) * sc) : 0.f;
                    e10 = act[mt][0] ? __expf((d[nt][mt][2] - gmx[nt][1]) * sc) : 0.f;
                    e11 = act[mt][1] ? __expf((d[nt][mt][3] - gmx[nt][1]) * sc) : 0.f;
                }
                rs[nt][0] += e00 + e01;
                rs[nt][1] += e10 + e11;
                *reinterpret_cast<float2 *>(&op[blo + mt * 8]) = make_float2(e00, e01);
                *reinterpret_cast<float2 *>(&op[bhi + mt * 8]) = make_float2(e10, e11);
            }
#pragma unroll
            for (int o = 1; o <= 2; o <<= 1) {
                rs[nt][0] += __shfl_xor_sync(0xffffffffu, rs[nt][0], o);
                rs[nt][1] += __shfl_xor_sync(0xffffffffu, rs[nt][1], o);
            }
            if (tig == 0) {
                RED[(wr * 32 + nt * 16 + g) * 8 + wc] = rs[nt][0];
                RED[(wr * 32 + nt * 16 + g + 8) * 8 + wc] = rs[nt][1];
            }
        }
        __syncthreads();
        if (tid < 64) {
            float t = 0.f;
#pragma unroll
            for (int i = 0; i < 8; i++) t += RED[tid * 8 + i];
            size_t nidx = (size_t)bk * NN + n0 + tid;
            if (p == 0) g_rsA[nidx] = hasAny ? (1.f / t) : 0.f;
            else        g_rsR[nidx] = 1.f / t;
        }
        __syncthreads();
    }
}

// ---------------- A@V via mma.sync tf32x3, cp.async pipelined ---------------------
// block 128n x 128d, 256 thr, 8 warps (nr 4 x dc 2); warp 32n x 64d; m chunks 32.
// smem: AS 2x(128x36), VS 2x(128x36), PSQ 256, NV 128
#define AV_VOFF  9216
#define AV_PSQO  18432
#define AV_NVO   18688
#define AV_FLOATS 18816
#define AV_BYTES (AV_FLOATS * 4)

template <int MODE>
__global__ __launch_bounds__(256, 2) void av_mma_kernel(
    const float *__restrict__ w1, const float *__restrict__ w2,
    const float *__restrict__ gb, const float *__restrict__ seed,
    const float *__restrict__ wcand, float *__restrict__ out) {
    extern __shared__ __align__(16) float sm[];
    float *PSQ = sm + AV_PSQO;
    float *NV  = sm + AV_NVO;
    uint32_t sb = smem_u32(sm);

    int bk = blockIdx.y, b = bk >> 3, kd = bk & 7;
    int n0 = blockIdx.x * 128;
    int tid = threadIdx.x, w = tid >> 5, lane = tid & 31;
    int nr = w & 3, dc = w >> 2;
    int g = lane >> 2, tig = lane & 3;

    const float *Ab = g_attn + (size_t)bk * NN * MM;
    const float *Vtb = g_Vt + (size_t)bk * DD * MM;

    float d[2][8][4];
#pragma unroll
    for (int nt = 0; nt < 2; nt++)
#pragma unroll
        for (int mt = 0; mt < 8; mt++)
#pragma unroll
            for (int c = 0; c < 4; c++) d[nt][mt][c] = 0.f;

    auto prefetch = [&](int mc, int st) {
#pragma unroll
        for (int i = 0; i < 4; i++) {       // attn: 128 rows x 32 m
            int f = tid + i * 256;
            int row = f >> 3, q = f & 7;
            cp_async16(sb + (st * 4608 + row * 36 + q * 4) * 4,
                       Ab + (size_t)(n0 + row) * MM + mc * 32 + q * 4);
        }
#pragma unroll
        for (int i = 0; i < 4; i++) {       // Vt: 128 d x 32 m
            int f = tid + i * 256;
            int dr = f >> 3, q = f & 7;
            cp_async16(sb + (AV_VOFF + st * 4608 + dr * 36 + q * 4) * 4,
                       Vtb + (size_t)dr * MM + mc * 32 + q * 4);
        }
        CP_COMMIT();
    };

    prefetch(0, 0);
    for (int mc = 0; mc < 16; mc++) {
        int st = mc & 1;
        if (mc < 15) { prefetch(mc + 1, st ^ 1); CP_WAIT(1); }
        else         { CP_WAIT(0); }
        __syncthreads();
        const float *Ast = sm + st * 4608;
        const float *Vst = sm + AV_VOFF + st * 4608;
#pragma unroll
        for (int ks = 0; ks < 4; ks++) {
            int k0 = ks * 8;
            uint32_t ahi[2][4], alo[2][4];
#pragma unroll
            for (int nt = 0; nt < 2; nt++) {
                int base = (nr * 32 + nt * 16 + g) * 36 + k0 + tig;
                float r0 = Ast[base], r1 = Ast[base + 8 * 36];
                float r2 = Ast[base + 4], r3 = Ast[base + 8 * 36 + 4];
                float h, l;
                tf32_split(r0, h, l); ahi[nt][0] = __float_as_uint(h); alo[nt][0] = __float_as_uint(l);
                tf32_split(r1, h, l); ahi[nt][1] = __float_as_uint(h); alo[nt][1] = __float_as_uint(l);
                tf32_split(r2, h, l); ahi[nt][2] = __float_as_uint(h); alo[nt][2] = __float_as_uint(l);
                tf32_split(r3, h, l); ahi[nt][3] = __float_as_uint(h); alo[nt][3] = __float_as_uint(l);
            }
#pragma unroll
            for (int mt = 0; mt < 8; mt++) {
                int bb = (dc * 64 + mt * 8 + g) * 36 + k0 + tig;
                float q0 = Vst[bb], q1 = Vst[bb + 4];
                float h0, l0, h1, l1;
                tf32_split(q0, h0, l0);
                tf32_split(q1, h1, l1);
                uint32_t bh0 = __float_as_uint(h0), bl0 = __float_as_uint(l0);
                uint32_t bh1 = __float_as_uint(h1), bl1 = __float_as_uint(l1);
#pragma unroll
                for (int nt = 0; nt < 2; nt++) {
                    mma1688(d[nt][mt], ahi[nt], bh0, bh1);
                    mma1688(d[nt][mt], ahi[nt], bl0, bl1);
                    mma1688(d[nt][mt], alo[nt], bh0, bh1);
                }
            }
        }
        __syncthreads();
    }

    // ---- epilogue -------------------------------------------------------------
    if (MODE == 0 || MODE == 1) {
        float2 w1c[8], w2c[8], gbc[8];
#pragma unroll
        for (int mt = 0; mt < 8; mt++) {
            int d2 = dc * 64 + mt * 8 + tig * 2;
            w1c[mt] = *reinterpret_cast<const float2 *>(&w1[kd * DD + d2]);
            w2c[mt] = *reinterpret_cast<const float2 *>(&w2[kd * DD + d2]);
            gbc[mt] = *reinterpret_cast<const float2 *>(&gb[kd * DD + d2]);
        }
#pragma unroll
        for (int nt = 0; nt < 2; nt++)
#pragma unroll
            for (int hf = 0; hf < 2; hf++) {
                int row = nr * 32 + nt * 16 + g + hf * 8;
                int n = n0 + row;
                float s = g_rsA[(size_t)bk * NN + n];
                size_t yb = ((size_t)bk * NN + n) * DD;
#pragma unroll
                for (int mt = 0; mt < 8; mt++) {
                    int d2 = dc * 64 + mt * 8 + tig * 2;
                    float2 yo = *reinterpret_cast<const float2 *>(&g_y[yb + d2]);
                    float dl0 = s * d[nt][mt][hf * 2];
                    float dl1 = s * d[nt][mt][hf * 2 + 1];
                    float g0 = sigmoidf(w1c[mt].x * yo.x + w2c[mt].x * dl0 + gbc[mt].x);
                    float g1 = sigmoidf(w1c[mt].y * yo.y + w2c[mt].y * dl1 + gbc[mt].y);
                    float2 yn = make_float2(yo.x + g0 * dl0, yo.y + g1 * dl1);
                    if (MODE == 0) {
                        *reinterpret_cast<float2 *>(&g_y[yb + d2]) = yn;
                    } else {
                        float2 sd = *reinterpret_cast<const float2 *>(
                            &seed[((size_t)b * NN + n) * DD + d2]);
                        *reinterpret_cast<float2 *>(
                            &out[OFF_YEM + (((size_t)b * NN + n) * NB + kd) * DD + d2]) =
                            make_float2(yn.x - sd.x, yn.y - sd.y);
                    }
                }
            }
    } else {
        // psq partials
#pragma unroll
        for (int nt = 0; nt < 2; nt++)
#pragma unroll
            for (int hf = 0; hf < 2; hf++) {
                int row = nr * 32 + nt * 16 + g + hf * 8;
                int n = n0 + row;
                float s = g_rsA[(size_t)bk * NN + n];
                size_t wb = ((size_t)b * NN + n) * DD;
                float p = 0.f;
#pragma unroll
                for (int mt = 0; mt < 8; mt++) {
                    int d2 = dc * 64 + mt * 8 + tig * 2;
                    float2 wv = *reinterpret_cast<const float2 *>(&wcand[wb + d2]);
                    float r0 = wv.x - s * d[nt][mt][hf * 2];
                    float r1 = wv.y - s * d[nt][mt][hf * 2 + 1];
                    p += r0 * r0 + r1 * r1;
                }
                p += __shfl_xor_sync(0xffffffffu, p, 1);
                p += __shfl_xor_sync(0xffffffffu, p, 2);
                if (tig == 0) PSQ[row * 2 + dc] = p;
            }
        __syncthreads();
        if (tid < 128) {
            int n = n0 + tid;
            float nv = 0.5f * g_surp[b * NN + n] +
                       0.5f * sqrtf(PSQ[tid * 2] + PSQ[tid * 2 + 1]);
            NV[tid] = nv;
            g_nov[bk * NN + n] = nv;
        }
        __syncthreads();
#pragma unroll
        for (int nt = 0; nt < 2; nt++)
#pragma unroll
            for (int hf = 0; hf < 2; hf++) {
                int row = nr * 32 + nt * 16 + g + hf * 8;
                int n = n0 + row;
                float nv = NV[row];
                float rsR = g_rsR[(size_t)bk * NN + n];
                float np2 = nv * rsR;
                size_t wb = ((size_t)b * NN + n) * DD;
                size_t ob = OFF_DEM + (((size_t)b * NN + n) * NB + kd) * DD;
                size_t so = ((size_t)bk * NN + n) * DD;
#pragma unroll
                for (int mt = 0; mt < 8; mt++) {
                    int d2 = dc * 64 + mt * 8 + tig * 2;
                    float2 wv = *reinterpret_cast<const float2 *>(&wcand[wb + d2]);
                    float2 wn = *reinterpret_cast<const float2 *>(&g_wnorm[wb + d2]);
                    float2 dem = make_float2(nv * wv.x, nv * wv.y);
                    *reinterpret_cast<float2 *>(&out[ob + d2]) = dem;
                    *reinterpret_cast<float2 *>(&g_WcS[so + d2]) =
                        make_float2(rsR * dem.x, rsR * dem.y);
                    *reinterpret_cast<float2 *>(&g_WnS[so + d2]) =
                        make_float2(np2 * wn.x, np2 * wn.y);
                }
            }
    }
}

// ---------------- swr partial ------------------------------------------------------
__global__ __launch_bounds__(256) void swr_kernel() {
    int bk = blockIdx.x, chunk = blockIdx.y;
    int t = threadIdx.x;
    float2 acc = make_float2(0.f, 0.f);
#pragma unroll 4
    for (int i = 0; i < 256; i++) {
        int n = chunk * 256 + i;
        float novp = g_nov[bk * NN + n] * g_rsR[bk * NN + n];
        float2 e = *reinterpret_cast<const float2 *>(
            &g_route[((size_t)bk * NN + n) * MM + t * 2]);
        acc.x += novp * e.x;
        acc.y += novp * e.y;
    }
    *reinterpret_cast<float2 *>(&g_swrP[(chunk * NBK + bk) * MM + t * 2]) = acc;
}

// ---------------- update_K / update_V pure GEMM (SIMT) ------------------------------
__global__ __launch_bounds__(256, 2) void updkv_kernel() {
    __shared__ __align__(16) float WRs[32][72];
    __shared__ __align__(16) float WnSs[32][132];
    __shared__ __align__(16) float WcSs[32][132];
    int bk = blockIdx.y;
    int m0 = blockIdx.x * 64;
    int tid = threadIdx.x, wid = tid >> 5, tx = tid & 31;

    float2 aK[8][2], aV[8][2];
#pragma unroll
    for (int r = 0; r < 8; r++) {
        aK[r][0] = make_float2(0.f, 0.f); aK[r][1] = make_float2(0.f, 0.f);
        aV[r][0] = make_float2(0.f, 0.f); aV[r][1] = make_float2(0.f, 0.f);
    }

    for (int n0 = 0; n0 < NN; n0 += 32) {
#pragma unroll
        for (int i = 0; i < 2; i++) {
            int idx = tid + i * 256;
            int nn = idx >> 4, q = idx & 15;
            *reinterpret_cast<float4 *>(&WRs[nn][q * 4]) =
                *reinterpret_cast<const float4 *>(
                    &g_route[((size_t)bk * NN + n0 + nn) * MM + m0 + q * 4]);
        }
#pragma unroll
        for (int i = 0; i < 4; i++) {
            int idx = tid + i * 256;
            int nn = idx >> 5, dq = idx & 31;
            size_t base = ((size_t)bk * NN + n0 + nn) * DD + dq * 4;
            *reinterpret_cast<float4 *>(&WnSs[nn][dq * 4]) =
                *reinterpret_cast<const float4 *>(&g_WnS[base]);
            *reinterpret_cast<float4 *>(&WcSs[nn][dq * 4]) =
                *reinterpret_cast<const float4 *>(&g_WcS[base]);
        }
        __syncthreads();
#pragma unroll
        for (int nn = 0; nn < 32; nn++) {
            float4 e0 = *reinterpret_cast<const float4 *>(&WRs[nn][wid * 8]);
            float4 e1 = *reinterpret_cast<const float4 *>(&WRs[nn][wid * 8 + 4]);
            float er[8] = {e0.x, e0.y, e0.z, e0.w, e1.x, e1.y, e1.z, e1.w};
            float4 wn = *reinterpret_cast<const float4 *>(&WnSs[nn][tx * 4]);
            float4 wc = *reinterpret_cast<const float4 *>(&WcSs[nn][tx * 4]);
            float2 nlo = make_float2(wn.x, wn.y), nhi = make_float2(wn.z, wn.w);
            float2 clo = make_float2(wc.x, wc.y), chi = make_float2(wc.z, wc.w);
#pragma unroll
            for (int r = 0; r < 8; r++) {
                float2 ep = make_float2(er[r], er[r]);
                fma2(aK[r][0], ep, nlo);
                fma2(aK[r][1], ep, nhi);
                fma2(aV[r][0], ep, clo);
                fma2(aV[r][1], ep, chi);
            }
        }
        __syncthreads();
    }
#pragma unroll
    for (int r = 0; r < 8; r++) {
        int m = m0 + wid * 8 + r;
        size_t off = ((size_t)bk * MM + m) * DD + tx * 4;
        *reinterpret_cast<float4 *>(&g_updK[off]) =
            make_float4(aK[r][0].x, aK[r][0].y, aK[r][1].x, aK[r][1].y);
        *reinterpret_cast<float4 *>(&g_updV[off]) =
            make_float4(aV[r][0].x, aV[r][0].y, aV[r][1].x, aV[r][1].y);
    }
}

// ---------------- final ---------------------------------------------------------------
__global__ __launch_bounds__(256) void final_kernel(
    const float *__restrict__ emK, const float *__restrict__ emV,
    const float *__restrict__ emS, const float *__restrict__ emAge,
    const float *__restrict__ gem, float *__restrict__ out) {
    int bk = blockIdx.x, b = bk >> 3, k = bk & 7;
    int tid = threadIdx.x, warp = tid >> 5, lane = tid & 31;
    float ge = gem[b * NB + k];
    const float invN = 1.f / (float)NN;

    for (int m = warp; m < MM; m += 8) {
        float swv = g_swrP[bk * MM + m] + g_swrP[NBK * MM + bk * MM + m]
                  + g_swrP[2 * NBK * MM + bk * MM + m]
                  + g_swrP[3 * NBK * MM + bk * MM + m];
        float denom = fmaxf(swv, 1e-8f);
        float alpha = fminf(ge * swv * invN, 1.f);
        float oma = 1.f - alpha;
        float idn = 1.f / denom;
        size_t off = ((size_t)bk * MM + m) * DD + lane * 4;
        float4 uk = *reinterpret_cast<const float4 *>(&g_updK[off]);
        uk.x *= idn; uk.y *= idn; uk.z *= idn; uk.w *= idn;
        float sq = uk.x * uk.x + uk.y * uk.y + uk.z * uk.z + uk.w * uk.w;
#pragma unroll
        for (int o = 16; o; o >>= 1) sq += __shfl_xor_sync(0xffffffffu, sq, o);
        float inv = 1.f / fmaxf(sqrtf(sq), 1e-12f);
        float ai = alpha * inv;
        float4 ek = *reinterpret_cast<const float4 *>(&emK[off]);
        *reinterpret_cast<float4 *>(&out[OFF_K + off]) =
            make_float4(oma * ek.x + ai * uk.x, oma * ek.y + ai * uk.y,
                        oma * ek.z + ai * uk.z, oma * ek.w + ai * uk.w);
        float4 uv = *reinterpret_cast<const float4 *>(&g_updV[off]);
        uv.x *= idn; uv.y *= idn; uv.z *= idn; uv.w *= idn;
        float4 ev = *reinterpret_cast<const float4 *>(&emV[off]);
        *reinterpret_cast<float4 *>(&out[OFF_V + off]) =
            make_float4(oma * ev.x + alpha * uv.x, oma * ev.y + alpha * uv.y,
                        oma * ev.z + alpha * uv.z, oma * ev.w + alpha * uv.w);
    }

    __shared__ float red[8];
    __shared__ float stot;
    float part = 0.f, sn[2], al[2];
#pragma unroll
    for (int i = 0; i < 2; i++) {
        int m = tid + i * 256;
        float swv = g_swrP[bk * MM + m] + g_swrP[NBK * MM + bk * MM + m]
                  + g_swrP[2 * NBK * MM + bk * MM + m]
                  + g_swrP[3 * NBK * MM + bk * MM + m];
        al[i] = fminf(ge * swv * invN, 1.f);
        float v = emS[bk * MM + m] + al[i];
        v = fminf(fmaxf(v, 0.f), 3.0f);
        sn[i] = v; part += v;
    }
#pragma unroll
    for (int o = 16; o; o >>= 1) part += __shfl_xor_sync(0xffffffffu, part, o);
    if (lane == 0) red[warp] = part;
    __syncthreads();
    if (tid == 0) {
        float t = 0.f;
        for (int i = 0; i < 8; i++) t += red[i];
        stot = t;
    }
    __syncthreads();
    float scale = fminf(1.f, 32.0f / fmaxf(stot, 1e-8f));
#pragma unroll
    for (int i = 0; i < 2; i++) {
        int m = tid + i * 256;
        out[OFF_S + bk * MM + m] = sn[i] * scale;
        out[OFF_AGE + bk * MM + m] = emAge[bk * MM + m] * (1.f - al[i]);
    }
}

// ---------------- launcher --------------------------------------------------------------
extern "C" void kernel_launch(void *const *d_in, const int *in_sizes, int n_in,
                              void *d_out, int out_size) {
    const float *seed     = (const float *)d_in[0];
    const float *wcand    = (const float *)d_in[1];
    const float *surprise = (const float *)d_in[2];
    const float *gem      = (const float *)d_in[3];
    const float *emK      = (const float *)d_in[4];
    const float *emV      = (const float *)d_in[5];
    const float *emS      = (const float *)d_in[6];
    const float *emAge    = (const float *)d_in[7];
    const float *w1       = (const float *)d_in[8];
    const float *w2       = (const float *)d_in[9];
    const float *gb       = (const float *)d_in[10];
    const float *rtau     = (const float *)d_in[11];
    const float *rtauw    = (const float *)d_in[12];
    float *out = (float *)d_out;

    cudaFuncSetAttribute(scores_mma_kernel<0>,
                         cudaFuncAttributeMaxDynamicSharedMemorySize, SC_BYTES);
    cudaFuncSetAttribute(scores_mma_kernel<1>,
                         cudaFuncAttributeMaxDynamicSharedMemorySize, SC_BYTES);
    cudaFuncSetAttribute(av_mma_kernel<0>,
                         cudaFuncAttributeMaxDynamicSharedMemorySize, AV_BYTES);
    cudaFuncSetAttribute(av_mma_kernel<1>,
                         cudaFuncAttributeMaxDynamicSharedMemorySize, AV_BYTES);
    cudaFuncSetAttribute(av_mma_kernel<2>,
                         cudaFuncAttributeMaxDynamicSharedMemorySize, AV_BYTES);

    dim3 gS(16, 64), gA(8, 64), gU(8, 64);
    dim3 gT(16, 4, 64), bT(32, 8);

    transpose_v_kernel<<<gT, bT>>>(emV);
    init_y_kernel<<<8192, 256>>>(seed);
    wnorm_kernel<<<8192, 128>>>(wcand, surprise);

    scores_mma_kernel<0><<<gS, 512, SC_BYTES>>>(emK, emS, rtau, rtauw);
    av_mma_kernel<0><<<gA, 256, AV_BYTES>>>(w1, w2, gb, seed, wcand, out);
    scores_mma_kernel<0><<<gS, 512, SC_BYTES>>>(emK, emS, rtau, rtauw);
    av_mma_kernel<1><<<gA, 256, AV_BYTES>>>(w1, w2, gb, seed, wcand, out);

    scores_mma_kernel<1><<<gS, 512, SC_BYTES>>>(emK, emS, rtau, rtauw);
    av_mma_kernel<2><<<gA, 256, AV_BYTES>>>(w1, w2, gb, seed, wcand, out);

    swr_kernel<<<dim3(64, 4), 256>>>();
    updkv_kernel<<<gU, 256>>>();
    final_kernel<<<64, 256>>>(emK, emV, emS, emAge, gem, out);
}

// round 8
// speedup vs baseline: 1.1956x; 1.0656x over previous
#include <cuda_runtime.h>
#include <math.h>
#include <stdint.h>

#define BSZ 8
#define NB  8
#define MM  512
#define DD  128
#define NN  1024
#define NBK 64
#define NEGV (-1e30f)

#define OFF_YEM 0
#define OFF_DEM 8388608
#define OFF_K   16777216
#define OFF_V   20971520
#define OFF_S   25165824
#define OFF_AGE 25198592

// ---------------- scratch -----------------------------------------------------
__device__ float g_y[NBK * NN * DD];
__device__ float g_attn[NBK * NN * MM];    // UNNORMALIZED exp
__device__ float g_route[NBK * NN * MM];   // UNNORMALIZED exp
__device__ float g_wnorm[BSZ * NN * DD];
__device__ float g_surp[BSZ * NN];
__device__ float g_novp[NBK * NN];         // novelty * rsR
__device__ float g_rsA[NBK * NN];
__device__ float g_rsR[NBK * NN];
__device__ float g_updK[NBK * MM * DD];
__device__ float g_updV[NBK * MM * DD];
__device__ float g_swrP[4 * NBK * MM];
__device__ float g_Vt[NBK * DD * MM];      // em_V transposed (bk, d, m)

// ---------------- helpers -----------------------------------------------------
__device__ __forceinline__ float softplusf(float x) {
    return (x > 20.f) ? x : log1pf(expf(x));
}
__device__ __forceinline__ float sigmoidf(float x) {
    return 1.f / (1.f + __expf(-x));
}
__device__ __forceinline__ void tf32_split(float x, float &hi, float &lo) {
    uint32_t h;
    asm("cvt.rna.tf32.f32 %0, %1;" : "=r"(h) : "f"(x));
    hi = __uint_as_float(h);
    lo = x - hi;
}
__device__ __forceinline__ uint32_t tf32_cvt(float x) {
    uint32_t h;
    asm("cvt.rna.tf32.f32 %0, %1;" : "=r"(h) : "f"(x));
    return h;
}
__device__ __forceinline__ uint32_t smem_u32(const void *p) {
    uint32_t a;
    asm("{ .reg .u64 t; cvta.to.shared.u64 t, %1; cvt.u32.u64 %0, t; }"
        : "=r"(a) : "l"(p));
    return a;
}
__device__ __forceinline__ void cp_async16(uint32_t saddr, const void *gaddr) {
    asm volatile("cp.async.cg.shared.global [%0], [%1], 16;"
                 :: "r"(saddr), "l"(gaddr) : "memory");
}
#define CP_COMMIT() asm volatile("cp.async.commit_group;" ::: "memory")
#define CP_WAIT(n)  asm volatile("cp.async.wait_group %0;" :: "n"(n) : "memory")

__device__ __forceinline__ void mma1688(float d[4], const uint32_t a[4],
                                        uint32_t b0, uint32_t b1) {
    asm volatile(
        "mma.sync.aligned.m16n8k8.row.col.f32.tf32.tf32.f32 "
        "{%0,%1,%2,%3}, {%4,%5,%6,%7}, {%8,%9}, {%0,%1,%2,%3};"
        : "+f"(d[0]), "+f"(d[1]), "+f"(d[2]), "+f"(d[3])
        : "r"(a[0]), "r"(a[1]), "r"(a[2]), "r"(a[3]), "r"(b0), "r"(b1));
}

// ---------------- V transpose: g_Vt[bk][d][m] = emV[bk][m][d] -------------------
__global__ void transpose_v_kernel(const float *__restrict__ emV) {
    __shared__ float t[32][33];
    int bk = blockIdx.z;
    int m0 = blockIdx.x * 32, d0 = blockIdx.y * 32;
    int x = threadIdx.x, y0 = threadIdx.y;
#pragma unroll
    for (int yy = 0; yy < 32; yy += 8)
        t[y0 + yy][x] = emV[((size_t)bk * MM + m0 + y0 + yy) * DD + d0 + x];
    __syncthreads();
#pragma unroll
    for (int yy = 0; yy < 32; yy += 8)
        g_Vt[((size_t)bk * DD + d0 + y0 + yy) * MM + m0 + x] = t[x][y0 + yy];
}

// ---------------- y init --------------------------------------------------------
__global__ void init_y_kernel(const float *__restrict__ seed) {
    int i = blockIdx.x * 256 + threadIdx.x;
    int bk = i >> 15;
    int rem = i & 32767;
    int b = bk >> 3;
    reinterpret_cast<float4 *>(g_y)[i] =
        reinterpret_cast<const float4 *>(seed)[b * 32768 + rem];
}

// ---------------- w_norm + surprise magnitude ------------------------------------
__global__ void wnorm_kernel(const float *__restrict__ wc,
                             const float *__restrict__ sp) {
    int row = blockIdx.x;
    int tid = threadIdx.x;
    float w = wc[row * DD + tid];
    float s = sp[row * DD + tid];
    float a = w * w, bb = s * s;
#pragma unroll
    for (int o = 16; o; o >>= 1) {
        a  += __shfl_xor_sync(0xffffffffu, a, o);
        bb += __shfl_xor_sync(0xffffffffu, bb, o);
    }
    __shared__ float ra[4], rb[4];
    if ((tid & 31) == 0) { ra[tid >> 5] = a; rb[tid >> 5] = bb; }
    __syncthreads();
    float na = ra[0] + ra[1] + ra[2] + ra[3];
    float nb = rb[0] + rb[1] + rb[2] + rb[3];
    g_wnorm[row * DD + tid] = w / fmaxf(sqrtf(na), 1e-12f);
    if (tid == 0) g_surp[row] = sqrtf(nb);
}

// ---------------- scores via mma.sync tf32x3, cp.async pipelined ------------------
#define SC_YOFF  36864
#define SC_REDO  41472
#define SC_SSVO  41984
#define SC_FLOATS 42496
#define SC_BYTES (SC_FLOATS * 4)

template <int MODE>
__global__ __launch_bounds__(512) void scores_mma_kernel(
    const float *__restrict__ emK, const float *__restrict__ emS,
    const float *__restrict__ rtau, const float *__restrict__ rtauw) {
    extern __shared__ __align__(16) float sm[];
    float *RED = sm + SC_REDO;
    float *SSV = sm + SC_SSVO;
    uint32_t sb = smem_u32(sm);

    int bk = blockIdx.y, b = bk >> 3, k = bk & 7;
    int n0 = blockIdx.x * 64;
    int tid = threadIdx.x, w = tid >> 5, lane = tid & 31;
    int wr = w >> 3, wc = w & 7;
    int g = lane >> 2, tig = lane & 3;

    const float *Yb = (MODE == 0) ? (g_y + (size_t)bk * NN * DD)
                                  : (g_wnorm + (size_t)b * NN * DD);
    const float *Kb = emK + (size_t)bk * MM * DD;

    float d[2][8][4];
#pragma unroll
    for (int nt = 0; nt < 2; nt++)
#pragma unroll
        for (int mt = 0; mt < 8; mt++)
#pragma unroll
            for (int c = 0; c < 4; c++) d[nt][mt][c] = 0.f;

    auto prefetch = [&](int kc, int st) {
#pragma unroll
        for (int i = 0; i < 8; i++) {
            int f = tid + i * 512;
            int m = f >> 3, q = f & 7;
            cp_async16(sb + (st * 18432 + m * 36 + q * 4) * 4,
                       Kb + (size_t)m * DD + kc * 32 + q * 4);
        }
        {
            int row = tid >> 3, q = tid & 7;
            cp_async16(sb + (SC_YOFF + st * 2304 + row * 36 + q * 4) * 4,
                       Yb + (size_t)(n0 + row) * DD + kc * 32 + q * 4);
        }
        CP_COMMIT();
    };

    prefetch(0, 0);
    for (int kc = 0; kc < 4; kc++) {
        int st = kc & 1;
        if (kc < 3) { prefetch(kc + 1, st ^ 1); CP_WAIT(1); }
        else        { CP_WAIT(0); }
        __syncthreads();
        const float *Kst = sm + st * 18432;
        const float *Yst = sm + SC_YOFF + st * 2304;
#pragma unroll
        for (int ks = 0; ks < 4; ks++) {
            int k0 = ks * 8;
            uint32_t ahi[2][4], alo[2][4];
#pragma unroll
            for (int nt = 0; nt < 2; nt++) {
                int base = (wr * 32 + nt * 16 + g) * 36 + k0 + tig;
                float r0 = Yst[base], r1 = Yst[base + 8 * 36];
                float r2 = Yst[base + 4], r3 = Yst[base + 8 * 36 + 4];
                float h, l;
                tf32_split(r0, h, l); ahi[nt][0] = __float_as_uint(h); alo[nt][0] = __float_as_uint(l);
                tf32_split(r1, h, l); ahi[nt][1] = __float_as_uint(h); alo[nt][1] = __float_as_uint(l);
                tf32_split(r2, h, l); ahi[nt][2] = __float_as_uint(h); alo[nt][2] = __float_as_uint(l);
                tf32_split(r3, h, l); ahi[nt][3] = __float_as_uint(h); alo[nt][3] = __float_as_uint(l);
            }
#pragma unroll
            for (int mt = 0; mt < 8; mt++) {
                int bb = (wc * 64 + mt * 8 + g) * 36 + k0 + tig;
                float q0 = Kst[bb], q1 = Kst[bb + 4];
                float h0, l0, h1, l1;
                tf32_split(q0, h0, l0);
                tf32_split(q1, h1, l1);
                uint32_t bh0 = __float_as_uint(h0), bl0 = __float_as_uint(l0);
                uint32_t bh1 = __float_as_uint(h1), bl1 = __float_as_uint(l1);
#pragma unroll
                for (int nt = 0; nt < 2; nt++) {
                    mma1688(d[nt][mt], ahi[nt], bh0, bh1);
                    mma1688(d[nt][mt], ahi[nt], bl0, bl1);
                    mma1688(d[nt][mt], alo[nt], bh0, bh1);
                }
            }
        }
        __syncthreads();
    }

    // ---- epilogue -------------------------------------------------------------
    float sv = emS[bk * MM + tid];
    SSV[tid] = sv;
    int hasAny = __syncthreads_or(sv > 0.f);

    bool act[8][2];
#pragma unroll
    for (int mt = 0; mt < 8; mt++) {
        int c = wc * 64 + mt * 8 + tig * 2;
        act[mt][0] = SSV[c] > 0.f;
        act[mt][1] = SSV[c + 1] > 0.f;
    }
    float inv_tau  = 1.f / (softplusf(rtau[k]) + 0.1f);
    float inv_tauw = 1.f / (softplusf(rtauw[k]) + 0.1f);

#pragma unroll
    for (int nt = 0; nt < 2; nt++) {
        float m0 = NEGV, m1 = NEGV;
#pragma unroll
        for (int mt = 0; mt < 8; mt++) {
            if (act[mt][0]) { m0 = fmaxf(m0, d[nt][mt][0]); m1 = fmaxf(m1, d[nt][mt][2]); }
            if (act[mt][1]) { m0 = fmaxf(m0, d[nt][mt][1]); m1 = fmaxf(m1, d[nt][mt][3]); }
        }
#pragma unroll
        for (int o = 1; o <= 2; o <<= 1) {
            m0 = fmaxf(m0, __shfl_xor_sync(0xffffffffu, m0, o));
            m1 = fmaxf(m1, __shfl_xor_sync(0xffffffffu, m1, o));
        }
        if (tig == 0) {
            RED[(wr * 32 + nt * 16 + g) * 8 + wc] = m0;
            RED[(wr * 32 + nt * 16 + g + 8) * 8 + wc] = m1;
        }
    }
    __syncthreads();
    float gmx[2][2];
#pragma unroll
    for (int nt = 0; nt < 2; nt++)
#pragma unroll
        for (int h = 0; h < 2; h++) {
            int r = wr * 32 + nt * 16 + g + h * 8;
            float m = RED[r * 8];
#pragma unroll
            for (int i = 1; i < 8; i++) m = fmaxf(m, RED[r * 8 + i]);
            gmx[nt][h] = m;
        }
    __syncthreads();

    int np = (MODE == 1) ? 2 : 1;
    for (int p = 0; p < np; p++) {
        float sc = (p == 0) ? inv_tau : inv_tauw;
        float *op = (p == 0) ? g_attn : g_route;
        float rs[2][2] = {{0.f, 0.f}, {0.f, 0.f}};
#pragma unroll
        for (int nt = 0; nt < 2; nt++) {
            int rlo = n0 + wr * 32 + nt * 16 + g;
            size_t blo = ((size_t)bk * NN + rlo) * MM + wc * 64 + tig * 2;
            size_t bhi = blo + 8 * MM;
#pragma unroll
            for (int mt = 0; mt < 8; mt++) {
                float e00, e01, e10, e11;
                if (!hasAny) { e00 = e01 = e10 = e11 = 1.f; }
                else {
                    e00 = act[mt][0] ? __expf((d[nt][mt][0] - gmx[nt][0]) * sc) : 0.f;
                    e01 = act[mt][1] ? __expf((d[nt][mt][1] - gmx[nt][0]) * sc) : 0.f;
                    e10 = act[mt][0] ? __expf((d[nt][mt][2] - gmx[nt][1]) * sc) : 0.f;
                    e11 = act[mt][1] ? __expf((d[nt][mt][3] - gmx[nt][1]) * sc) : 0.f;
                }
                rs[nt][0] += e00 + e01;
                rs[nt][1] += e10 + e11;
                *reinterpret_cast<float2 *>(&op[blo + mt * 8]) = make_float2(e00, e01);
                *reinterpret_cast<float2 *>(&op[bhi + mt * 8]) = make_float2(e10, e11);
            }
#pragma unroll
            for (int o = 1; o <= 2; o <<= 1) {
                rs[nt][0] += __shfl_xor_sync(0xffffffffu, rs[nt][0], o);
                rs[nt][1] += __shfl_xor_sync(0xffffffffu, rs[nt][1], o);
            }
            if (tig == 0) {
                RED[(wr * 32 + nt * 16 + g) * 8 + wc] = rs[nt][0];
                RED[(wr * 32 + nt * 16 + g + 8) * 8 + wc] = rs[nt][1];
            }
        }
        __syncthreads();
        if (tid < 64) {
            float t = 0.f;
#pragma unroll
            for (int i = 0; i < 8; i++) t += RED[tid * 8 + i];
            size_t nidx = (size_t)bk * NN + n0 + tid;
            if (p == 0) g_rsA[nidx] = hasAny ? (1.f / t) : 0.f;
            else        g_rsR[nidx] = 1.f / t;
        }
        __syncthreads();
    }
}

// ---------------- A@V via mma.sync tf32x3, cp.async pipelined ---------------------
#define AV_VOFF  9216
#define AV_PSQO  18432
#define AV_NVO   18688
#define AV_FLOATS 18816
#define AV_BYTES (AV_FLOATS * 4)

template <int MODE>
__global__ __launch_bounds__(256, 2) void av_mma_kernel(
    const float *__restrict__ w1, const float *__restrict__ w2,
    const float *__restrict__ gb, const float *__restrict__ seed,
    const float *__restrict__ wcand, float *__restrict__ out) {
    extern __shared__ __align__(16) float sm[];
    float *PSQ = sm + AV_PSQO;
    float *NV  = sm + AV_NVO;
    uint32_t sb = smem_u32(sm);

    int bk = blockIdx.y, b = bk >> 3, kd = bk & 7;
    int n0 = blockIdx.x * 128;
    int tid = threadIdx.x, w = tid >> 5, lane = tid & 31;
    int nr = w & 3, dc = w >> 2;
    int g = lane >> 2, tig = lane & 3;

    const float *Ab = g_attn + (size_t)bk * NN * MM;
    const float *Vtb = g_Vt + (size_t)bk * DD * MM;

    float d[2][8][4];
#pragma unroll
    for (int nt = 0; nt < 2; nt++)
#pragma unroll
        for (int mt = 0; mt < 8; mt++)
#pragma unroll
            for (int c = 0; c < 4; c++) d[nt][mt][c] = 0.f;

    auto prefetch = [&](int mc, int st) {
#pragma unroll
        for (int i = 0; i < 4; i++) {
            int f = tid + i * 256;
            int row = f >> 3, q = f & 7;
            cp_async16(sb + (st * 4608 + row * 36 + q * 4) * 4,
                       Ab + (size_t)(n0 + row) * MM + mc * 32 + q * 4);
        }
#pragma unroll
        for (int i = 0; i < 4; i++) {
            int f = tid + i * 256;
            int dr = f >> 3, q = f & 7;
            cp_async16(sb + (AV_VOFF + st * 4608 + dr * 36 + q * 4) * 4,
                       Vtb + (size_t)dr * MM + mc * 32 + q * 4);
        }
        CP_COMMIT();
    };

    prefetch(0, 0);
    for (int mc = 0; mc < 16; mc++) {
        int st = mc & 1;
        if (mc < 15) { prefetch(mc + 1, st ^ 1); CP_WAIT(1); }
        else         { CP_WAIT(0); }
        __syncthreads();
        const float *Ast = sm + st * 4608;
        const float *Vst = sm + AV_VOFF + st * 4608;
#pragma unroll
        for (int ks = 0; ks < 4; ks++) {
            int k0 = ks * 8;
            uint32_t ahi[2][4], alo[2][4];
#pragma unroll
            for (int nt = 0; nt < 2; nt++) {
                int base = (nr * 32 + nt * 16 + g) * 36 + k0 + tig;
                float r0 = Ast[base], r1 = Ast[base + 8 * 36];
                float r2 = Ast[base + 4], r3 = Ast[base + 8 * 36 + 4];
                float h, l;
                tf32_split(r0, h, l); ahi[nt][0] = __float_as_uint(h); alo[nt][0] = __float_as_uint(l);
                tf32_split(r1, h, l); ahi[nt][1] = __float_as_uint(h); alo[nt][1] = __float_as_uint(l);
                tf32_split(r2, h, l); ahi[nt][2] = __float_as_uint(h); alo[nt][2] = __float_as_uint(l);
                tf32_split(r3, h, l); ahi[nt][3] = __float_as_uint(h); alo[nt][3] = __float_as_uint(l);
            }
#pragma unroll
            for (int mt = 0; mt < 8; mt++) {
                int bb = (dc * 64 + mt * 8 + g) * 36 + k0 + tig;
                float q0 = Vst[bb], q1 = Vst[bb + 4];
                float h0, l0, h1, l1;
                tf32_split(q0, h0, l0);
                tf32_split(q1, h1, l1);
                uint32_t bh0 = __float_as_uint(h0), bl0 = __float_as_uint(l0);
                uint32_t bh1 = __float_as_uint(h1), bl1 = __float_as_uint(l1);
#pragma unroll
                for (int nt = 0; nt < 2; nt++) {
                    mma1688(d[nt][mt], ahi[nt], bh0, bh1);
                    mma1688(d[nt][mt], ahi[nt], bl0, bl1);
                    mma1688(d[nt][mt], alo[nt], bh0, bh1);
                }
            }
        }
        __syncthreads();
    }

    // ---- epilogue -------------------------------------------------------------
    if (MODE == 0 || MODE == 1) {
        float2 w1c[8], w2c[8], gbc[8];
#pragma unroll
        for (int mt = 0; mt < 8; mt++) {
            int d2 = dc * 64 + mt * 8 + tig * 2;
            w1c[mt] = *reinterpret_cast<const float2 *>(&w1[kd * DD + d2]);
            w2c[mt] = *reinterpret_cast<const float2 *>(&w2[kd * DD + d2]);
            gbc[mt] = *reinterpret_cast<const float2 *>(&gb[kd * DD + d2]);
        }
#pragma unroll
        for (int nt = 0; nt < 2; nt++)
#pragma unroll
            for (int hf = 0; hf < 2; hf++) {
                int row = nr * 32 + nt * 16 + g + hf * 8;
                int n = n0 + row;
                float s = g_rsA[(size_t)bk * NN + n];
                size_t yb = ((size_t)bk * NN + n) * DD;
#pragma unroll
                for (int mt = 0; mt < 8; mt++) {
                    int d2 = dc * 64 + mt * 8 + tig * 2;
                    float2 yo = *reinterpret_cast<const float2 *>(&g_y[yb + d2]);
                    float dl0 = s * d[nt][mt][hf * 2];
                    float dl1 = s * d[nt][mt][hf * 2 + 1];
                    float g0 = sigmoidf(w1c[mt].x * yo.x + w2c[mt].x * dl0 + gbc[mt].x);
                    float g1 = sigmoidf(w1c[mt].y * yo.y + w2c[mt].y * dl1 + gbc[mt].y);
                    float2 yn = make_float2(yo.x + g0 * dl0, yo.y + g1 * dl1);
                    if (MODE == 0) {
                        *reinterpret_cast<float2 *>(&g_y[yb + d2]) = yn;
                    } else {
                        float2 sd = *reinterpret_cast<const float2 *>(
                            &seed[((size_t)b * NN + n) * DD + d2]);
                        *reinterpret_cast<float2 *>(
                            &out[OFF_YEM + (((size_t)b * NN + n) * NB + kd) * DD + d2]) =
                            make_float2(yn.x - sd.x, yn.y - sd.y);
                    }
                }
            }
    } else {
#pragma unroll
        for (int nt = 0; nt < 2; nt++)
#pragma unroll
            for (int hf = 0; hf < 2; hf++) {
                int row = nr * 32 + nt * 16 + g + hf * 8;
                int n = n0 + row;
                float s = g_rsA[(size_t)bk * NN + n];
                size_t wb = ((size_t)b * NN + n) * DD;
                float p = 0.f;
#pragma unroll
                for (int mt = 0; mt < 8; mt++) {
                    int d2 = dc * 64 + mt * 8 + tig * 2;
                    float2 wv = *reinterpret_cast<const float2 *>(&wcand[wb + d2]);
                    float r0 = wv.x - s * d[nt][mt][hf * 2];
                    float r1 = wv.y - s * d[nt][mt][hf * 2 + 1];
                    p += r0 * r0 + r1 * r1;
                }
                p += __shfl_xor_sync(0xffffffffu, p, 1);
                p += __shfl_xor_sync(0xffffffffu, p, 2);
                if (tig == 0) PSQ[row * 2 + dc] = p;
            }
        __syncthreads();
        if (tid < 128) {
            int n = n0 + tid;
            float nv = 0.5f * g_surp[b * NN + n] +
                       0.5f * sqrtf(PSQ[tid * 2] + PSQ[tid * 2 + 1]);
            NV[tid] = nv;
            g_novp[(size_t)bk * NN + n] = nv * g_rsR[(size_t)bk * NN + n];
        }
        __syncthreads();
#pragma unroll
        for (int nt = 0; nt < 2; nt++)
#pragma unroll
            for (int hf = 0; hf < 2; hf++) {
                int row = nr * 32 + nt * 16 + g + hf * 8;
                int n = n0 + row;
                float nv = NV[row];
                size_t wb = ((size_t)b * NN + n) * DD;
                size_t ob = OFF_DEM + (((size_t)b * NN + n) * NB + kd) * DD;
#pragma unroll
                for (int mt = 0; mt < 8; mt++) {
                    int d2 = dc * 64 + mt * 8 + tig * 2;
                    float2 wv = *reinterpret_cast<const float2 *>(&wcand[wb + d2]);
                    *reinterpret_cast<float2 *>(&out[ob + d2]) =
                        make_float2(nv * wv.x, nv * wv.y);
                }
            }
    }
}

// ---------------- swr partial ------------------------------------------------------
__global__ __launch_bounds__(256) void swr_kernel() {
    int bk = blockIdx.x, chunk = blockIdx.y;
    int t = threadIdx.x;
    float2 acc = make_float2(0.f, 0.f);
#pragma unroll 4
    for (int i = 0; i < 256; i++) {
        int n = chunk * 256 + i;
        float novp = g_novp[(size_t)bk * NN + n];
        float2 e = *reinterpret_cast<const float2 *>(
            &g_route[((size_t)bk * NN + n) * MM + t * 2]);
        acc.x += novp * e.x;
        acc.y += novp * e.y;
    }
    *reinterpret_cast<float2 *>(&g_swrP[(chunk * NBK + bk) * MM + t * 2]) = acc;
}

// ---------------- update_K / update_V via mma.sync (2-term tf32) ---------------------
// C[m,d] = sum_n (novp[n]*route[n,m]) * W[n,d]   for W = wnorm (K) and wcand (V).
// block 64m x 128d, 256 thr, 8 warps (mr 4 x dc 2); warp 16m x 64d; n chunks 32.
#define UK_WN   2176
#define UK_WC   6400
#define UK_NV   10624
#define UK_STAGE 10656
#define UK_FLOATS (2 * UK_STAGE)
#define UK_BYTES (UK_FLOATS * 4)

__global__ __launch_bounds__(256, 2) void updkv_mma_kernel(
    const float *__restrict__ wcand) {
    extern __shared__ __align__(16) float sm[];
    uint32_t sb = smem_u32(sm);

    int bk = blockIdx.y, b = bk >> 3;
    int m0 = blockIdx.x * 64;
    int tid = threadIdx.x, w = tid >> 5, lane = tid & 31;
    int mr = w & 3, dc = w >> 2;
    int g = lane >> 2, tig = lane & 3;

    const float *Rb = g_route + (size_t)bk * NN * MM;
    const float *Wnb = g_wnorm + (size_t)b * NN * DD;
    const float *Wcb = wcand + (size_t)b * NN * DD;
    const float *NPb = g_novp + (size_t)bk * NN;

    float dK[8][4], dV[8][4];
#pragma unroll
    for (int mt = 0; mt < 8; mt++)
#pragma unroll
        for (int c = 0; c < 4; c++) { dK[mt][c] = 0.f; dV[mt][c] = 0.f; }

    auto prefetch = [&](int nc, int st) {
        int base = st * UK_STAGE;
#pragma unroll
        for (int i = 0; i < 2; i++) {   // route tile 32n x 64m
            int f = tid + i * 256;
            int row = f >> 4, q = f & 15;
            cp_async16(sb + (base + row * 68 + q * 4) * 4,
                       Rb + (size_t)(nc * 32 + row) * MM + m0 + q * 4);
        }
#pragma unroll
        for (int i = 0; i < 4; i++) {   // wnorm tile 32n x 128d
            int f = tid + i * 256;
            int row = f >> 5, q = f & 31;
            cp_async16(sb + (base + UK_WN + row * 132 + q * 4) * 4,
                       Wnb + (size_t)(nc * 32 + row) * DD + q * 4);
        }
#pragma unroll
        for (int i = 0; i < 4; i++) {   // wcand tile 32n x 128d
            int f = tid + i * 256;
            int row = f >> 5, q = f & 31;
            cp_async16(sb + (base + UK_WC + row * 132 + q * 4) * 4,
                       Wcb + (size_t)(nc * 32 + row) * DD + q * 4);
        }
        if (tid < 8)                    // novp 32 floats
            cp_async16(sb + (base + UK_NV + tid * 4) * 4,
                       NPb + nc * 32 + tid * 4);
        CP_COMMIT();
    };

    prefetch(0, 0);
    for (int nc = 0; nc < 32; nc++) {
        int st = nc & 1;
        if (nc < 31) { prefetch(nc + 1, st ^ 1); CP_WAIT(1); }
        else         { CP_WAIT(0); }
        __syncthreads();
        const float *RT = sm + st * UK_STAGE;
        const float *WN = RT + UK_WN;
        const float *WC = RT + UK_WC;
        const float *NV = RT + UK_NV;
#pragma unroll
        for (int ks = 0; ks < 4; ks++) {
            int k0 = ks * 8;
            float nv0 = NV[k0 + tig], nv1 = NV[k0 + tig + 4];
            int ar = mr * 16 + g;
            uint32_t A[4];
            A[0] = tf32_cvt(RT[(k0 + tig) * 68 + ar] * nv0);
            A[1] = tf32_cvt(RT[(k0 + tig) * 68 + ar + 8] * nv0);
            A[2] = tf32_cvt(RT[(k0 + tig + 4) * 68 + ar] * nv1);
            A[3] = tf32_cvt(RT[(k0 + tig + 4) * 68 + ar + 8] * nv1);
#pragma unroll
            for (int mt = 0; mt < 8; mt++) {
                int db = dc * 64 + mt * 8 + g;
                float n0f = WN[(k0 + tig) * 132 + db];
                float n1f = WN[(k0 + tig + 4) * 132 + db];
                float c0f = WC[(k0 + tig) * 132 + db];
                float c1f = WC[(k0 + tig + 4) * 132 + db];
                float nh0, nl0, nh1, nl1, ch0, cl0, ch1, cl1;
                tf32_split(n0f, nh0, nl0); tf32_split(n1f, nh1, nl1);
                tf32_split(c0f, ch0, cl0); tf32_split(c1f, ch1, cl1);
                mma1688(dK[mt], A, __float_as_uint(nh0), __float_as_uint(nh1));
                mma1688(dK[mt], A, __float_as_uint(nl0), __float_as_uint(nl1));
                mma1688(dV[mt], A, __float_as_uint(ch0), __float_as_uint(ch1));
                mma1688(dV[mt], A, __float_as_uint(cl0), __float_as_uint(cl1));
            }
        }
        __syncthreads();
    }

#pragma unroll
    for (int mt = 0; mt < 8; mt++) {
        int m_row = m0 + mr * 16 + g;
        int d2 = dc * 64 + mt * 8 + tig * 2;
        size_t o0 = ((size_t)bk * MM + m_row) * DD + d2;
        size_t o1 = ((size_t)bk * MM + m_row + 8) * DD + d2;
        *reinterpret_cast<float2 *>(&g_updK[o0]) = make_float2(dK[mt][0], dK[mt][1]);
        *reinterpret_cast<float2 *>(&g_updK[o1]) = make_float2(dK[mt][2], dK[mt][3]);
        *reinterpret_cast<float2 *>(&g_updV[o0]) = make_float2(dV[mt][0], dV[mt][1]);
        *reinterpret_cast<float2 *>(&g_updV[o1]) = make_float2(dV[mt][2], dV[mt][3]);
    }
}

// ---------------- final ---------------------------------------------------------------
__global__ __launch_bounds__(256) void final_kernel(
    const float *__restrict__ emK, const float *__restrict__ emV,
    const float *__restrict__ emS, const float *__restrict__ emAge,
    const float *__restrict__ gem, float *__restrict__ out) {
    int bk = blockIdx.x, b = bk >> 3, k = bk & 7;
    int tid = threadIdx.x, warp = tid >> 5, lane = tid & 31;
    float ge = gem[b * NB + k];
    const float invN = 1.f / (float)NN;

    for (int m = warp; m < MM; m += 8) {
        float swv = g_swrP[bk * MM + m] + g_swrP[NBK * MM + bk * MM + m]
                  + g_swrP[2 * NBK * MM + bk * MM + m]
                  + g_swrP[3 * NBK * MM + bk * MM + m];
        float denom = fmaxf(swv, 1e-8f);
        float alpha = fminf(ge * swv * invN, 1.f);
        float oma = 1.f - alpha;
        float idn = 1.f / denom;
        size_t off = ((size_t)bk * MM + m) * DD + lane * 4;
        float4 uk = *reinterpret_cast<const float4 *>(&g_updK[off]);
        uk.x *= idn; uk.y *= idn; uk.z *= idn; uk.w *= idn;
        float sq = uk.x * uk.x + uk.y * uk.y + uk.z * uk.z + uk.w * uk.w;
#pragma unroll
        for (int o = 16; o; o >>= 1) sq += __shfl_xor_sync(0xffffffffu, sq, o);
        float inv = 1.f / fmaxf(sqrtf(sq), 1e-12f);
        float ai = alpha * inv;
        float4 ek = *reinterpret_cast<const float4 *>(&emK[off]);
        *reinterpret_cast<float4 *>(&out[OFF_K + off]) =
            make_float4(oma * ek.x + ai * uk.x, oma * ek.y + ai * uk.y,
                        oma * ek.z + ai * uk.z, oma * ek.w + ai * uk.w);
        float4 uv = *reinterpret_cast<const float4 *>(&g_updV[off]);
        uv.x *= idn; uv.y *= idn; uv.z *= idn; uv.w *= idn;
        float4 ev = *reinterpret_cast<const float4 *>(&emV[off]);
        *reinterpret_cast<float4 *>(&out[OFF_V + off]) =
            make_float4(oma * ev.x + alpha * uv.x, oma * ev.y + alpha * uv.y,
                        oma * ev.z + alpha * uv.z, oma * ev.w + alpha * uv.w);
    }

    __shared__ float red[8];
    __shared__ float stot;
    float part = 0.f, sn[2], al[2];
#pragma unroll
    for (int i = 0; i < 2; i++) {
        int m = tid + i * 256;
        float swv = g_swrP[bk * MM + m] + g_swrP[NBK * MM + bk * MM + m]
                  + g_swrP[2 * NBK * MM + bk * MM + m]
                  + g_swrP[3 * NBK * MM + bk * MM + m];
        al[i] = fminf(ge * swv * invN, 1.f);
        float v = emS[bk * MM + m] + al[i];
        v = fminf(fmaxf(v, 0.f), 3.0f);
        sn[i] = v; part += v;
    }
#pragma unroll
    for (int o = 16; o; o >>= 1) part += __shfl_xor_sync(0xffffffffu, part, o);
    if (lane == 0) red[warp] = part;
    __syncthreads();
    if (tid == 0) {
        float t = 0.f;
        for (int i = 0; i < 8; i++) t += red[i];
        stot = t;
    }
    __syncthreads();
    float scale = fminf(1.f, 32.0f / fmaxf(stot, 1e-8f));
#pragma unroll
    for (int i = 0; i < 2; i++) {
        int m = tid + i * 256;
        out[OFF_S + bk * MM + m] = sn[i] * scale;
        out[OFF_AGE + bk * MM + m] = emAge[bk * MM + m] * (1.f - al[i]);
    }
}

// ---------------- launcher --------------------------------------------------------------
extern "C" void kernel_launch(void *const *d_in, const int *in_sizes, int n_in,
                              void *d_out, int out_size) {
    const float *seed     = (const float *)d_in[0];
    const float *wcand    = (const float *)d_in[1];
    const float *surprise = (const float *)d_in[2];
    const float *gem      = (const float *)d_in[3];
    const float *emK      = (const float *)d_in[4];
    const float *emV      = (const float *)d_in[5];
    const float *emS      = (const float *)d_in[6];
    const float *emAge    = (const float *)d_in[7];
    const float *w1       = (const float *)d_in[8];
    const float *w2       = (const float *)d_in[9];
    const float *gb       = (const float *)d_in[10];
    const float *rtau     = (const float *)d_in[11];
    const float *rtauw    = (const float *)d_in[12];
    float *out = (float *)d_out;

    cudaFuncSetAttribute(scores_mma_kernel<0>,
                         cudaFuncAttributeMaxDynamicSharedMemorySize, SC_BYTES);
    cudaFuncSetAttribute(scores_mma_kernel<1>,
                         cudaFuncAttributeMaxDynamicSharedMemorySize, SC_BYTES);
    cudaFuncSetAttribute(av_mma_kernel<0>,
                         cudaFuncAttributeMaxDynamicSharedMemorySize, AV_BYTES);
    cudaFuncSetAttribute(av_mma_kernel<1>,
                         cudaFuncAttributeMaxDynamicSharedMemorySize, AV_BYTES);
    cudaFuncSetAttribute(av_mma_kernel<2>,
                         cudaFuncAttributeMaxDynamicSharedMemorySize, AV_BYTES);
    cudaFuncSetAttribute(updkv_mma_kernel,
                         cudaFuncAttributeMaxDynamicSharedMemorySize, UK_BYTES);

    dim3 gS(16, 64), gA(8, 64), gU(8, 64);
    dim3 gT(16, 4, 64), bT(32, 8);

    transpose_v_kernel<<<gT, bT>>>(emV);
    init_y_kernel<<<8192, 256>>>(seed);
    wnorm_kernel<<<8192, 128>>>(wcand, surprise);

    scores_mma_kernel<0><<<gS, 512, SC_BYTES>>>(emK, emS, rtau, rtauw);
    av_mma_kernel<0><<<gA, 256, AV_BYTES>>>(w1, w2, gb, seed, wcand, out);
    scores_mma_kernel<0><<<gS, 512, SC_BYTES>>>(emK, emS, rtau, rtauw);
    av_mma_kernel<1><<<gA, 256, AV_BYTES>>>(w1, w2, gb, seed, wcand, out);

    scores_mma_kernel<1><<<gS, 512, SC_BYTES>>>(emK, emS, rtau, rtauw);
    av_mma_kernel<2><<<gA, 256, AV_BYTES>>>(w1, w2, gb, seed, wcand, out);

    swr_kernel<<<dim3(64, 4), 256>>>();
    updkv_mma_kernel<<<gU, 256, UK_BYTES>>>(wcand);
    final_kernel<<<64, 256>>>(emK, emV, emS, emAge, gem, out);
}

// round 9
// speedup vs baseline: 1.3939x; 1.1659x over previous
#include <cuda_runtime.h>
#include <cuda_fp16.h>
#include <math.h>
#include <stdint.h>

#define BSZ 8
#define NB  8
#define MM  512
#define DD  128
#define NN  1024
#define NBK 64
#define NEGV (-1e30f)

#define OFF_YEM 0
#define OFF_DEM 8388608
#define OFF_K   16777216
#define OFF_V   20971520
#define OFF_S   25165824
#define OFF_AGE 25198592

// ---------------- scratch -----------------------------------------------------
__device__ float g_y[NBK * NN * DD];
__device__ float g_attn[NBK * NN * MM];    // UNNORMALIZED exp
__device__ float g_route[NBK * NN * MM];   // UNNORMALIZED exp
__device__ float g_wnorm[BSZ * NN * DD];
__device__ float g_surp[BSZ * NN];
__device__ float g_novp[NBK * NN];         // novelty * rsR
__device__ float g_rsA[NBK * NN];
__device__ float g_rsR[NBK * NN];
__device__ float g_updK[NBK * MM * DD];
__device__ float g_updV[NBK * MM * DD];
__device__ float g_swrP[4 * NBK * MM];
__device__ float g_Vt[NBK * DD * MM];      // em_V transposed (bk, d, m)

// ---------------- helpers -----------------------------------------------------
__device__ __forceinline__ float softplusf(float x) {
    return (x > 20.f) ? x : log1pf(expf(x));
}
__device__ __forceinline__ float sigmoidf(float x) {
    return 1.f / (1.f + __expf(-x));
}
__device__ __forceinline__ void tf32_split(float x, float &hi, float &lo) {
    uint32_t h;
    asm("cvt.rna.tf32.f32 %0, %1;" : "=r"(h) : "f"(x));
    hi = __uint_as_float(h);
    lo = x - hi;
}
__device__ __forceinline__ uint32_t tf32_cvt(float x) {
    uint32_t h;
    asm("cvt.rna.tf32.f32 %0, %1;" : "=r"(h) : "f"(x));
    return h;
}
__device__ __forceinline__ uint32_t smem_u32(const void *p) {
    uint32_t a;
    asm("{ .reg .u64 t; cvta.to.shared.u64 t, %1; cvt.u32.u64 %0, t; }"
        : "=r"(a) : "l"(p));
    return a;
}
__device__ __forceinline__ void cp_async16(uint32_t saddr, const void *gaddr) {
    asm volatile("cp.async.cg.shared.global [%0], [%1], 16;"
                 :: "r"(saddr), "l"(gaddr) : "memory");
}
#define CP_COMMIT() asm volatile("cp.async.commit_group;" ::: "memory")
#define CP_WAIT(n)  asm volatile("cp.async.wait_group %0;" :: "n"(n) : "memory")

// tf32 m16n8k8 (updkv path)
__device__ __forceinline__ void mma1688(float d[4], const uint32_t a[4],
                                        uint32_t b0, uint32_t b1) {
    asm volatile(
        "mma.sync.aligned.m16n8k8.row.col.f32.tf32.tf32.f32 "
        "{%0,%1,%2,%3}, {%4,%5,%6,%7}, {%8,%9}, {%0,%1,%2,%3};"
        : "+f"(d[0]), "+f"(d[1]), "+f"(d[2]), "+f"(d[3])
        : "r"(a[0]), "r"(a[1]), "r"(a[2]), "r"(a[3]), "r"(b0), "r"(b1));
}
// fp16 m16n8k16
__device__ __forceinline__ void mma_f16(float d[4], const uint32_t a[4],
                                        uint32_t b0, uint32_t b1) {
    asm volatile(
        "mma.sync.aligned.m16n8k16.row.col.f32.f16.f16.f32 "
        "{%0,%1,%2,%3}, {%4,%5,%6,%7}, {%8,%9}, {%0,%1,%2,%3};"
        : "+f"(d[0]), "+f"(d[1]), "+f"(d[2]), "+f"(d[3])
        : "r"(a[0]), "r"(a[1]), "r"(a[2]), "r"(a[3]), "r"(b0), "r"(b1));
}
// split float4 -> packed fp16 hi pair-words + lo pair-words
__device__ __forceinline__ void split4(float4 x, uint32_t &h01, uint32_t &h23,
                                       uint32_t &l01, uint32_t &l23) {
    __half2 a = __float22half2_rn(make_float2(x.x, x.y));
    __half2 b = __float22half2_rn(make_float2(x.z, x.w));
    float2 fa = __half22float2(a);
    float2 fb = __half22float2(b);
    __half2 la = __float22half2_rn(make_float2(x.x - fa.x, x.y - fa.y));
    __half2 lb = __float22half2_rn(make_float2(x.z - fb.x, x.w - fb.y));
    h01 = *reinterpret_cast<uint32_t *>(&a);
    h23 = *reinterpret_cast<uint32_t *>(&b);
    l01 = *reinterpret_cast<uint32_t *>(&la);
    l23 = *reinterpret_cast<uint32_t *>(&lb);
}

// ---------------- V transpose --------------------------------------------------
__global__ void transpose_v_kernel(const float *__restrict__ emV) {
    __shared__ float t[32][33];
    int bk = blockIdx.z;
    int m0 = blockIdx.x * 32, d0 = blockIdx.y * 32;
    int x = threadIdx.x, y0 = threadIdx.y;
#pragma unroll
    for (int yy = 0; yy < 32; yy += 8)
        t[y0 + yy][x] = emV[((size_t)bk * MM + m0 + y0 + yy) * DD + d0 + x];
    __syncthreads();
#pragma unroll
    for (int yy = 0; yy < 32; yy += 8)
        g_Vt[((size_t)bk * DD + d0 + y0 + yy) * MM + m0 + x] = t[x][y0 + yy];
}

// ---------------- y init --------------------------------------------------------
__global__ void init_y_kernel(const float *__restrict__ seed) {
    int i = blockIdx.x * 256 + threadIdx.x;
    int bk = i >> 15;
    int rem = i & 32767;
    int b = bk >> 3;
    reinterpret_cast<float4 *>(g_y)[i] =
        reinterpret_cast<const float4 *>(seed)[b * 32768 + rem];
}

// ---------------- w_norm + surprise magnitude ------------------------------------
__global__ void wnorm_kernel(const float *__restrict__ wc,
                             const float *__restrict__ sp) {
    int row = blockIdx.x;
    int tid = threadIdx.x;
    float w = wc[row * DD + tid];
    float s = sp[row * DD + tid];
    float a = w * w, bb = s * s;
#pragma unroll
    for (int o = 16; o; o >>= 1) {
        a  += __shfl_xor_sync(0xffffffffu, a, o);
        bb += __shfl_xor_sync(0xffffffffu, bb, o);
    }
    __shared__ float ra[4], rb[4];
    if ((tid & 31) == 0) { ra[tid >> 5] = a; rb[tid >> 5] = bb; }
    __syncthreads();
    float na = ra[0] + ra[1] + ra[2] + ra[3];
    float nb = rb[0] + rb[1] + rb[2] + rb[3];
    g_wnorm[row * DD + tid] = w / fmaxf(sqrtf(na), 1e-12f);
    if (tid == 0) g_surp[row] = sqrtf(nb);
}

// ---------------- scores via fp16x3 mma, pre-split packed smem --------------------
// block 64n x 512m, 512 thr, 16 warps (wr 2 x wc 8); warp 32n x 64m; kd=16 chunks.
// smem (word offsets): raw K+Y double stage 2x9216; KH/KL 512x12; YH/YL 64x12.
#define SC_RAWSZ 9216
#define SC_KH    18432
#define SC_KL    24576
#define SC_YH    30720
#define SC_YL    31488
#define SC_RED   32256
#define SC_SSV   32768
#define SC_WORDS 33280
#define SC_BYTES (SC_WORDS * 4)

template <int MODE>
__global__ __launch_bounds__(512) void scores_mma_kernel(
    const float *__restrict__ emK, const float *__restrict__ emS,
    const float *__restrict__ rtau, const float *__restrict__ rtauw) {
    extern __shared__ __align__(16) float sm[];
    uint32_t *smU = reinterpret_cast<uint32_t *>(sm);
    float *RED = sm + SC_RED;
    float *SSV = sm + SC_SSV;
    uint32_t sb = smem_u32(sm);

    int bk = blockIdx.y, b = bk >> 3, k = bk & 7;
    int n0 = blockIdx.x * 64;
    int tid = threadIdx.x, w = tid >> 5, lane = tid & 31;
    int wr = w >> 3, wc = w & 7;
    int g = lane >> 2, tig = lane & 3;

    const float *Yb = (MODE == 0) ? (g_y + (size_t)bk * NN * DD)
                                  : (g_wnorm + (size_t)b * NN * DD);
    const float *Kb = emK + (size_t)bk * MM * DD;

    float d[2][8][4];
#pragma unroll
    for (int nt = 0; nt < 2; nt++)
#pragma unroll
        for (int mt = 0; mt < 8; mt++)
#pragma unroll
            for (int c = 0; c < 4; c++) d[nt][mt][c] = 0.f;

    auto prefetch = [&](int kc, int st) {
#pragma unroll
        for (int i = 0; i < 4; i++) {       // K: 512m x 16d raw
            int f = tid + i * 512;
            int m = f >> 2, q = f & 3;
            cp_async16(sb + (st * SC_RAWSZ + m * 16 + q * 4) * 4,
                       Kb + (size_t)m * DD + kc * 16 + q * 4);
        }
        if (tid < 256) {                    // Y: 64n x 16d raw
            int row = tid >> 2, q = tid & 3;
            cp_async16(sb + (st * SC_RAWSZ + 8192 + row * 16 + q * 4) * 4,
                       Yb + (size_t)(n0 + row) * DD + kc * 16 + q * 4);
        }
        CP_COMMIT();
    };

    prefetch(0, 0);
    prefetch(1, 1);
    for (int kc = 0; kc < 8; kc++) {
        int st = kc & 1;
        if (kc == 7) { CP_WAIT(0); } else { CP_WAIT(1); }
        __syncthreads();                    // raw ready; prev MMA done
        // ---- split phase: raw fp32 -> packed fp16 hi/lo
        const float *rawK = sm + st * SC_RAWSZ;
        const float *rawY = rawK + 8192;
#pragma unroll
        for (int i = 0; i < 4; i++) {
            int f = tid + i * 512;
            int m = f >> 2, q = f & 3;
            float4 x = *reinterpret_cast<const float4 *>(&rawK[m * 16 + q * 4]);
            uint32_t h01, h23, l01, l23;
            split4(x, h01, h23, l01, l23);
            *reinterpret_cast<uint2 *>(&smU[SC_KH + m * 12 + q * 2]) = make_uint2(h01, h23);
            *reinterpret_cast<uint2 *>(&smU[SC_KL + m * 12 + q * 2]) = make_uint2(l01, l23);
        }
        if (tid < 256) {
            int row = tid >> 2, q = tid & 3;
            float4 x = *reinterpret_cast<const float4 *>(&rawY[row * 16 + q * 4]);
            uint32_t h01, h23, l01, l23;
            split4(x, h01, h23, l01, l23);
            *reinterpret_cast<uint2 *>(&smU[SC_YH + row * 12 + q * 2]) = make_uint2(h01, h23);
            *reinterpret_cast<uint2 *>(&smU[SC_YL + row * 12 + q * 2]) = make_uint2(l01, l23);
        }
        __syncthreads();
        if (kc + 2 < 8) prefetch(kc + 2, st);
        // ---- MMA phase (pure LDS.32 + HMMA)
        uint32_t ah[2][4], al[2][4];
#pragma unroll
        for (int nt = 0; nt < 2; nt++) {
            int r0 = wr * 32 + nt * 16 + g;
            ah[nt][0] = smU[SC_YH + r0 * 12 + tig];
            ah[nt][1] = smU[SC_YH + (r0 + 8) * 12 + tig];
            ah[nt][2] = smU[SC_YH + r0 * 12 + tig + 4];
            ah[nt][3] = smU[SC_YH + (r0 + 8) * 12 + tig + 4];
            al[nt][0] = smU[SC_YL + r0 * 12 + tig];
            al[nt][1] = smU[SC_YL + (r0 + 8) * 12 + tig];
            al[nt][2] = smU[SC_YL + r0 * 12 + tig + 4];
            al[nt][3] = smU[SC_YL + (r0 + 8) * 12 + tig + 4];
        }
#pragma unroll
        for (int mt = 0; mt < 8; mt++) {
            int m = wc * 64 + mt * 8 + g;
            uint32_t bh0 = smU[SC_KH + m * 12 + tig];
            uint32_t bh1 = smU[SC_KH + m * 12 + tig + 4];
            uint32_t bl0 = smU[SC_KL + m * 12 + tig];
            uint32_t bl1 = smU[SC_KL + m * 12 + tig + 4];
#pragma unroll
            for (int nt = 0; nt < 2; nt++) {
                mma_f16(d[nt][mt], ah[nt], bh0, bh1);
                mma_f16(d[nt][mt], ah[nt], bl0, bl1);
                mma_f16(d[nt][mt], al[nt], bh0, bh1);
            }
        }
    }
    __syncthreads();

    // ---- epilogue (identical to verified R8 layout) ---------------------------
    float sv = emS[bk * MM + tid];
    SSV[tid] = sv;
    int hasAny = __syncthreads_or(sv > 0.f);

    bool act[8][2];
#pragma unroll
    for (int mt = 0; mt < 8; mt++) {
        int c = wc * 64 + mt * 8 + tig * 2;
        act[mt][0] = SSV[c] > 0.f;
        act[mt][1] = SSV[c + 1] > 0.f;
    }
    float inv_tau  = 1.f / (softplusf(rtau[k]) + 0.1f);
    float inv_tauw = 1.f / (softplusf(rtauw[k]) + 0.1f);

#pragma unroll
    for (int nt = 0; nt < 2; nt++) {
        float m0 = NEGV, m1 = NEGV;
#pragma unroll
        for (int mt = 0; mt < 8; mt++) {
            if (act[mt][0]) { m0 = fmaxf(m0, d[nt][mt][0]); m1 = fmaxf(m1, d[nt][mt][2]); }
            if (act[mt][1]) { m0 = fmaxf(m0, d[nt][mt][1]); m1 = fmaxf(m1, d[nt][mt][3]); }
        }
#pragma unroll
        for (int o = 1; o <= 2; o <<= 1) {
            m0 = fmaxf(m0, __shfl_xor_sync(0xffffffffu, m0, o));
            m1 = fmaxf(m1, __shfl_xor_sync(0xffffffffu, m1, o));
        }
        if (tig == 0) {
            RED[(wr * 32 + nt * 16 + g) * 8 + wc] = m0;
            RED[(wr * 32 + nt * 16 + g + 8) * 8 + wc] = m1;
        }
    }
    __syncthreads();
    float gmx[2][2];
#pragma unroll
    for (int nt = 0; nt < 2; nt++)
#pragma unroll
        for (int h = 0; h < 2; h++) {
            int r = wr * 32 + nt * 16 + g + h * 8;
            float m = RED[r * 8];
#pragma unroll
            for (int i = 1; i < 8; i++) m = fmaxf(m, RED[r * 8 + i]);
            gmx[nt][h] = m;
        }
    __syncthreads();

    int np = (MODE == 1) ? 2 : 1;
    for (int p = 0; p < np; p++) {
        float sc = (p == 0) ? inv_tau : inv_tauw;
        float *op = (p == 0) ? g_attn : g_route;
        float rs[2][2] = {{0.f, 0.f}, {0.f, 0.f}};
#pragma unroll
        for (int nt = 0; nt < 2; nt++) {
            int rlo = n0 + wr * 32 + nt * 16 + g;
            size_t blo = ((size_t)bk * NN + rlo) * MM + wc * 64 + tig * 2;
            size_t bhi = blo + 8 * MM;
#pragma unroll
            for (int mt = 0; mt < 8; mt++) {
                float e00, e01, e10, e11;
                if (!hasAny) { e00 = e01 = e10 = e11 = 1.f; }
                else {
                    e00 = act[mt][0] ? __expf((d[nt][mt][0] - gmx[nt][0]) * sc) : 0.f;
                    e01 = act[mt][1] ? __expf((d[nt][mt][1] - gmx[nt][0]) * sc) : 0.f;
                    e10 = act[mt][0] ? __expf((d[nt][mt][2] - gmx[nt][1]) * sc) : 0.f;
                    e11 = act[mt][1] ? __expf((d[nt][mt][3] - gmx[nt][1]) * sc) : 0.f;
                }
                rs[nt][0] += e00 + e01;
                rs[nt][1] += e10 + e11;
                *reinterpret_cast<float2 *>(&op[blo + mt * 8]) = make_float2(e00, e01);
                *reinterpret_cast<float2 *>(&op[bhi + mt * 8]) = make_float2(e10, e11);
            }
#pragma unroll
            for (int o = 1; o <= 2; o <<= 1) {
                rs[nt][0] += __shfl_xor_sync(0xffffffffu, rs[nt][0], o);
                rs[nt][1] += __shfl_xor_sync(0xffffffffu, rs[nt][1], o);
            }
            if (tig == 0) {
                RED[(wr * 32 + nt * 16 + g) * 8 + wc] = rs[nt][0];
                RED[(wr * 32 + nt * 16 + g + 8) * 8 + wc] = rs[nt][1];
            }
        }
        __syncthreads();
        if (tid < 64) {
            float t = 0.f;
#pragma unroll
            for (int i = 0; i < 8; i++) t += RED[tid * 8 + i];
            size_t nidx = (size_t)bk * NN + n0 + tid;
            if (p == 0) g_rsA[nidx] = hasAny ? (1.f / t) : 0.f;
            else        g_rsR[nidx] = 1.f / t;
        }
        __syncthreads();
    }
}

// ---------------- A@V via fp16x3 mma, pre-split packed smem -----------------------
// block 128n x 128d, 256 thr, 8 warps (nr 4 x dc 2); warp 32n x 64d; m chunks 16.
#define AV_RAWSZ 4096
#define AV_AH 8192
#define AV_AL 9728
#define AV_VH 11264
#define AV_VL 12800
#define AV_PSQ 14336
#define AV_NV 14592
#define AV_WORDS 14720
#define AV_BYTES (AV_WORDS * 4)

template <int MODE>
__global__ __launch_bounds__(256, 2) void av_mma_kernel(
    const float *__restrict__ w1, const float *__restrict__ w2,
    const float *__restrict__ gb, const float *__restrict__ seed,
    const float *__restrict__ wcand, float *__restrict__ out) {
    extern __shared__ __align__(16) float sm[];
    uint32_t *smU = reinterpret_cast<uint32_t *>(sm);
    float *PSQ = sm + AV_PSQ;
    float *NV  = sm + AV_NV;
    uint32_t sb = smem_u32(sm);

    int bk = blockIdx.y, b = bk >> 3, kd = bk & 7;
    int n0 = blockIdx.x * 128;
    int tid = threadIdx.x, w = tid >> 5, lane = tid & 31;
    int nr = w & 3, dc = w >> 2;
    int g = lane >> 2, tig = lane & 3;

    const float *Ab = g_attn + (size_t)bk * NN * MM;
    const float *Vtb = g_Vt + (size_t)bk * DD * MM;

    float d[2][8][4];
#pragma unroll
    for (int nt = 0; nt < 2; nt++)
#pragma unroll
        for (int mt = 0; mt < 8; mt++)
#pragma unroll
            for (int c = 0; c < 4; c++) d[nt][mt][c] = 0.f;

    auto prefetch = [&](int mc, int st) {
#pragma unroll
        for (int i = 0; i < 2; i++) {       // attn: 128n x 16m raw
            int f = tid + i * 256;
            int row = f >> 2, q = f & 3;
            cp_async16(sb + (st * AV_RAWSZ + row * 16 + q * 4) * 4,
                       Ab + (size_t)(n0 + row) * MM + mc * 16 + q * 4);
        }
#pragma unroll
        for (int i = 0; i < 2; i++) {       // Vt: 128d x 16m raw
            int f = tid + i * 256;
            int dr = f >> 2, q = f & 3;
            cp_async16(sb + (st * AV_RAWSZ + 2048 + dr * 16 + q * 4) * 4,
                       Vtb + (size_t)dr * MM + mc * 16 + q * 4);
        }
        CP_COMMIT();
    };

    prefetch(0, 0);
    prefetch(1, 1);
    for (int mc = 0; mc < 32; mc++) {
        int st = mc & 1;
        if (mc == 31) { CP_WAIT(0); } else { CP_WAIT(1); }
        __syncthreads();
        const float *rawA = sm + st * AV_RAWSZ;
        const float *rawV = rawA + 2048;
#pragma unroll
        for (int i = 0; i < 2; i++) {
            int f = tid + i * 256;
            int row = f >> 2, q = f & 3;
            float4 x = *reinterpret_cast<const float4 *>(&rawA[row * 16 + q * 4]);
            uint32_t h01, h23, l01, l23;
            split4(x, h01, h23, l01, l23);
            *reinterpret_cast<uint2 *>(&smU[AV_AH + row * 12 + q * 2]) = make_uint2(h01, h23);
            *reinterpret_cast<uint2 *>(&smU[AV_AL + row * 12 + q * 2]) = make_uint2(l01, l23);
        }
#pragma unroll
        for (int i = 0; i < 2; i++) {
            int f = tid + i * 256;
            int dr = f >> 2, q = f & 3;
            float4 x = *reinterpret_cast<const float4 *>(&rawV[dr * 16 + q * 4]);
            uint32_t h01, h23, l01, l23;
            split4(x, h01, h23, l01, l23);
            *reinterpret_cast<uint2 *>(&smU[AV_VH + dr * 12 + q * 2]) = make_uint2(h01, h23);
            *reinterpret_cast<uint2 *>(&smU[AV_VL + dr * 12 + q * 2]) = make_uint2(l01, l23);
        }
        __syncthreads();
        if (mc + 2 < 32) prefetch(mc + 2, st);
        uint32_t ah[2][4], al[2][4];
#pragma unroll
        for (int nt = 0; nt < 2; nt++) {
            int r0 = nr * 32 + nt * 16 + g;
            ah[nt][0] = smU[AV_AH + r0 * 12 + tig];
            ah[nt][1] = smU[AV_AH + (r0 + 8) * 12 + tig];
            ah[nt][2] = smU[AV_AH + r0 * 12 + tig + 4];
            ah[nt][3] = smU[AV_AH + (r0 + 8) * 12 + tig + 4];
            al[nt][0] = smU[AV_AL + r0 * 12 + tig];
            al[nt][1] = smU[AV_AL + (r0 + 8) * 12 + tig];
            al[nt][2] = smU[AV_AL + r0 * 12 + tig + 4];
            al[nt][3] = smU[AV_AL + (r0 + 8) * 12 + tig + 4];
        }
#pragma unroll
        for (int mt = 0; mt < 8; mt++) {
            int dr = dc * 64 + mt * 8 + g;
            uint32_t bh0 = smU[AV_VH + dr * 12 + tig];
            uint32_t bh1 = smU[AV_VH + dr * 12 + tig + 4];
            uint32_t bl0 = smU[AV_VL + dr * 12 + tig];
            uint32_t bl1 = smU[AV_VL + dr * 12 + tig + 4];
#pragma unroll
            for (int nt = 0; nt < 2; nt++) {
                mma_f16(d[nt][mt], ah[nt], bh0, bh1);
                mma_f16(d[nt][mt], ah[nt], bl0, bl1);
                mma_f16(d[nt][mt], al[nt], bh0, bh1);
            }
        }
    }
    __syncthreads();

    // ---- epilogue (identical to verified R8) -----------------------------------
    if (MODE == 0 || MODE == 1) {
        float2 w1c[8], w2c[8], gbc[8];
#pragma unroll
        for (int mt = 0; mt < 8; mt++) {
            int d2 = dc * 64 + mt * 8 + tig * 2;
            w1c[mt] = *reinterpret_cast<const float2 *>(&w1[kd * DD + d2]);
            w2c[mt] = *reinterpret_cast<const float2 *>(&w2[kd * DD + d2]);
            gbc[mt] = *reinterpret_cast<const float2 *>(&gb[kd * DD + d2]);
        }
#pragma unroll
        for (int nt = 0; nt < 2; nt++)
#pragma unroll
            for (int hf = 0; hf < 2; hf++) {
                int row = nr * 32 + nt * 16 + g + hf * 8;
                int n = n0 + row;
                float s = g_rsA[(size_t)bk * NN + n];
                size_t yb = ((size_t)bk * NN + n) * DD;
#pragma unroll
                for (int mt = 0; mt < 8; mt++) {
                    int d2 = dc * 64 + mt * 8 + tig * 2;
                    float2 yo = *reinterpret_cast<const float2 *>(&g_y[yb + d2]);
                    float dl0 = s * d[nt][mt][hf * 2];
                    float dl1 = s * d[nt][mt][hf * 2 + 1];
                    float g0 = sigmoidf(w1c[mt].x * yo.x + w2c[mt].x * dl0 + gbc[mt].x);
                    float g1 = sigmoidf(w1c[mt].y * yo.y + w2c[mt].y * dl1 + gbc[mt].y);
                    float2 yn = make_float2(yo.x + g0 * dl0, yo.y + g1 * dl1);
                    if (MODE == 0) {
                        *reinterpret_cast<float2 *>(&g_y[yb + d2]) = yn;
                    } else {
                        float2 sd = *reinterpret_cast<const float2 *>(
                            &seed[((size_t)b * NN + n) * DD + d2]);
                        *reinterpret_cast<float2 *>(
                            &out[OFF_YEM + (((size_t)b * NN + n) * NB + kd) * DD + d2]) =
                            make_float2(yn.x - sd.x, yn.y - sd.y);
                    }
                }
            }
    } else {
#pragma unroll
        for (int nt = 0; nt < 2; nt++)
#pragma unroll
            for (int hf = 0; hf < 2; hf++) {
                int row = nr * 32 + nt * 16 + g + hf * 8;
                int n = n0 + row;
                float s = g_rsA[(size_t)bk * NN + n];
                size_t wb = ((size_t)b * NN + n) * DD;
                float p = 0.f;
#pragma unroll
                for (int mt = 0; mt < 8; mt++) {
                    int d2 = dc * 64 + mt * 8 + tig * 2;
                    float2 wv = *reinterpret_cast<const float2 *>(&wcand[wb + d2]);
                    float r0 = wv.x - s * d[nt][mt][hf * 2];
                    float r1 = wv.y - s * d[nt][mt][hf * 2 + 1];
                    p += r0 * r0 + r1 * r1;
                }
                p += __shfl_xor_sync(0xffffffffu, p, 1);
                p += __shfl_xor_sync(0xffffffffu, p, 2);
                if (tig == 0) PSQ[row * 2 + dc] = p;
            }
        __syncthreads();
        if (tid < 128) {
            int n = n0 + tid;
            float nv = 0.5f * g_surp[b * NN + n] +
                       0.5f * sqrtf(PSQ[tid * 2] + PSQ[tid * 2 + 1]);
            NV[tid] = nv;
            g_novp[(size_t)bk * NN + n] = nv * g_rsR[(size_t)bk * NN + n];
        }
        __syncthreads();
#pragma unroll
        for (int nt = 0; nt < 2; nt++)
#pragma unroll
            for (int hf = 0; hf < 2; hf++) {
                int row = nr * 32 + nt * 16 + g + hf * 8;
                int n = n0 + row;
                float nv = NV[row];
                size_t wb = ((size_t)b * NN + n) * DD;
                size_t ob = OFF_DEM + (((size_t)b * NN + n) * NB + kd) * DD;
#pragma unroll
                for (int mt = 0; mt < 8; mt++) {
                    int d2 = dc * 64 + mt * 8 + tig * 2;
                    float2 wv = *reinterpret_cast<const float2 *>(&wcand[wb + d2]);
                    *reinterpret_cast<float2 *>(&out[ob + d2]) =
                        make_float2(nv * wv.x, nv * wv.y);
                }
            }
    }
}

// ---------------- swr partial ------------------------------------------------------
__global__ __launch_bounds__(256) void swr_kernel() {
    int bk = blockIdx.x, chunk = blockIdx.y;
    int t = threadIdx.x;
    float2 acc = make_float2(0.f, 0.f);
#pragma unroll 4
    for (int i = 0; i < 256; i++) {
        int n = chunk * 256 + i;
        float novp = g_novp[(size_t)bk * NN + n];
        float2 e = *reinterpret_cast<const float2 *>(
            &g_route[((size_t)bk * NN + n) * MM + t * 2]);
        acc.x += novp * e.x;
        acc.y += novp * e.y;
    }
    *reinterpret_cast<float2 *>(&g_swrP[(chunk * NBK + bk) * MM + t * 2]) = acc;
}

// ---------------- update_K / update_V via mma.sync (2-term tf32) ---------------------
#define UK_WN   2176
#define UK_WC   6400
#define UK_NV   10624
#define UK_STAGE 10656
#define UK_FLOATS (2 * UK_STAGE)
#define UK_BYTES (UK_FLOATS * 4)

__global__ __launch_bounds__(256, 2) void updkv_mma_kernel(
    const float *__restrict__ wcand) {
    extern __shared__ __align__(16) float sm[];
    uint32_t sb = smem_u32(sm);

    int bk = blockIdx.y, b = bk >> 3;
    int m0 = blockIdx.x * 64;
    int tid = threadIdx.x, w = tid >> 5, lane = tid & 31;
    int mr = w & 3, dc = w >> 2;
    int g = lane >> 2, tig = lane & 3;

    const float *Rb = g_route + (size_t)bk * NN * MM;
    const float *Wnb = g_wnorm + (size_t)b * NN * DD;
    const float *Wcb = wcand + (size_t)b * NN * DD;
    const float *NPb = g_novp + (size_t)bk * NN;

    float dK[8][4], dV[8][4];
#pragma unroll
    for (int mt = 0; mt < 8; mt++)
#pragma unroll
        for (int c = 0; c < 4; c++) { dK[mt][c] = 0.f; dV[mt][c] = 0.f; }

    auto prefetch = [&](int nc, int st) {
        int base = st * UK_STAGE;
#pragma unroll
        for (int i = 0; i < 2; i++) {
            int f = tid + i * 256;
            int row = f >> 4, q = f & 15;
            cp_async16(sb + (base + row * 68 + q * 4) * 4,
                       Rb + (size_t)(nc * 32 + row) * MM + m0 + q * 4);
        }
#pragma unroll
        for (int i = 0; i < 4; i++) {
            int f = tid + i * 256;
            int row = f >> 5, q = f & 31;
            cp_async16(sb + (base + UK_WN + row * 132 + q * 4) * 4,
                       Wnb + (size_t)(nc * 32 + row) * DD + q * 4);
        }
#pragma unroll
        for (int i = 0; i < 4; i++) {
            int f = tid + i * 256;
            int row = f >> 5, q = f & 31;
            cp_async16(sb + (base + UK_WC + row * 132 + q * 4) * 4,
                       Wcb + (size_t)(nc * 32 + row) * DD + q * 4);
        }
        if (tid < 8)
            cp_async16(sb + (base + UK_NV + tid * 4) * 4,
                       NPb + nc * 32 + tid * 4);
        CP_COMMIT();
    };

    prefetch(0, 0);
    for (int nc = 0; nc < 32; nc++) {
        int st = nc & 1;
        if (nc < 31) { prefetch(nc + 1, st ^ 1); CP_WAIT(1); }
        else         { CP_WAIT(0); }
        __syncthreads();
        const float *RT = sm + st * UK_STAGE;
        const float *WN = RT + UK_WN;
        const float *WC = RT + UK_WC;
        const float *NV = RT + UK_NV;
#pragma unroll
        for (int ks = 0; ks < 4; ks++) {
            int k0 = ks * 8;
            float nv0 = NV[k0 + tig], nv1 = NV[k0 + tig + 4];
            int ar = mr * 16 + g;
            uint32_t A[4];
            A[0] = tf32_cvt(RT[(k0 + tig) * 68 + ar] * nv0);
            A[1] = tf32_cvt(RT[(k0 + tig) * 68 + ar + 8] * nv0);
            A[2] = tf32_cvt(RT[(k0 + tig + 4) * 68 + ar] * nv1);
            A[3] = tf32_cvt(RT[(k0 + tig + 4) * 68 + ar + 8] * nv1);
#pragma unroll
            for (int mt = 0; mt < 8; mt++) {
                int db = dc * 64 + mt * 8 + g;
                float n0f = WN[(k0 + tig) * 132 + db];
                float n1f = WN[(k0 + tig + 4) * 132 + db];
                float c0f = WC[(k0 + tig) * 132 + db];
                float c1f = WC[(k0 + tig + 4) * 132 + db];
                float nh0, nl0, nh1, nl1, ch0, cl0, ch1, cl1;
                tf32_split(n0f, nh0, nl0); tf32_split(n1f, nh1, nl1);
                tf32_split(c0f, ch0, cl0); tf32_split(c1f, ch1, cl1);
                mma1688(dK[mt], A, __float_as_uint(nh0), __float_as_uint(nh1));
                mma1688(dK[mt], A, __float_as_uint(nl0), __float_as_uint(nl1));
                mma1688(dV[mt], A, __float_as_uint(ch0), __float_as_uint(ch1));
                mma1688(dV[mt], A, __float_as_uint(cl0), __float_as_uint(cl1));
            }
        }
        __syncthreads();
    }

#pragma unroll
    for (int mt = 0; mt < 8; mt++) {
        int m_row = m0 + mr * 16 + g;
        int d2 = dc * 64 + mt * 8 + tig * 2;
        size_t o0 = ((size_t)bk * MM + m_row) * DD + d2;
        size_t o1 = ((size_t)bk * MM + m_row + 8) * DD + d2;
        *reinterpret_cast<float2 *>(&g_updK[o0]) = make_float2(dK[mt][0], dK[mt][1]);
        *reinterpret_cast<float2 *>(&g_updK[o1]) = make_float2(dK[mt][2], dK[mt][3]);
        *reinterpret_cast<float2 *>(&g_updV[o0]) = make_float2(dV[mt][0], dV[mt][1]);
        *reinterpret_cast<float2 *>(&g_updV[o1]) = make_float2(dV[mt][2], dV[mt][3]);
    }
}

// ---------------- final ---------------------------------------------------------------
__global__ __launch_bounds__(256) void final_kernel(
    const float *__restrict__ emK, const float *__restrict__ emV,
    const float *__restrict__ emS, const float *__restrict__ emAge,
    const float *__restrict__ gem, float *__restrict__ out) {
    int bk = blockIdx.x, b = bk >> 3, k = bk & 7;
    int tid = threadIdx.x, warp = tid >> 5, lane = tid & 31;
    float ge = gem[b * NB + k];
    const float invN = 1.f / (float)NN;

    for (int m = warp; m < MM; m += 8) {
        float swv = g_swrP[bk * MM + m] + g_swrP[NBK * MM + bk * MM + m]
                  + g_swrP[2 * NBK * MM + bk * MM + m]
                  + g_swrP[3 * NBK * MM + bk * MM + m];
        float denom = fmaxf(swv, 1e-8f);
        float alpha = fminf(ge * swv * invN, 1.f);
        float oma = 1.f - alpha;
        float idn = 1.f / denom;
        size_t off = ((size_t)bk * MM + m) * DD + lane * 4;
        float4 uk = *reinterpret_cast<const float4 *>(&g_updK[off]);
        uk.x *= idn; uk.y *= idn; uk.z *= idn; uk.w *= idn;
        float sq = uk.x * uk.x + uk.y * uk.y + uk.z * uk.z + uk.w * uk.w;
#pragma unroll
        for (int o = 16; o; o >>= 1) sq += __shfl_xor_sync(0xffffffffu, sq, o);
        float inv = 1.f / fmaxf(sqrtf(sq), 1e-12f);
        float ai = alpha * inv;
        float4 ek = *reinterpret_cast<const float4 *>(&emK[off]);
        *reinterpret_cast<float4 *>(&out[OFF_K + off]) =
            make_float4(oma * ek.x + ai * uk.x, oma * ek.y + ai * uk.y,
                        oma * ek.z + ai * uk.z, oma * ek.w + ai * uk.w);
        float4 uv = *reinterpret_cast<const float4 *>(&g_updV[off]);
        uv.x *= idn; uv.y *= idn; uv.z *= idn; uv.w *= idn;
        float4 ev = *reinterpret_cast<const float4 *>(&emV[off]);
        *reinterpret_cast<float4 *>(&out[OFF_V + off]) =
            make_float4(oma * ev.x + alpha * uv.x, oma * ev.y + alpha * uv.y,
                        oma * ev.z + alpha * uv.z, oma * ev.w + alpha * uv.w);
    }

    __shared__ float red[8];
    __shared__ float stot;
    float part = 0.f, sn[2], al[2];
#pragma unroll
    for (int i = 0; i < 2; i++) {
        int m = tid + i * 256;
        float swv = g_swrP[bk * MM + m] + g_swrP[NBK * MM + bk * MM + m]
                  + g_swrP[2 * NBK * MM + bk * MM + m]
                  + g_swrP[3 * NBK * MM + bk * MM + m];
        al[i] = fminf(ge * swv * invN, 1.f);
        float v = emS[bk * MM + m] + al[i];
        v = fminf(fmaxf(v, 0.f), 3.0f);
        sn[i] = v; part += v;
    }
#pragma unroll
    for (int o = 16; o; o >>= 1) part += __shfl_xor_sync(0xffffffffu, part, o);
    if (lane == 0) red[warp] = part;
    __syncthreads();
    if (tid == 0) {
        float t = 0.f;
        for (int i = 0; i < 8; i++) t += red[i];
        stot = t;
    }
    __syncthreads();
    float scale = fminf(1.f, 32.0f / fmaxf(stot, 1e-8f));
#pragma unroll
    for (int i = 0; i < 2; i++) {
        int m = tid + i * 256;
        out[OFF_S + bk * MM + m] = sn[i] * scale;
        out[OFF_AGE + bk * MM + m] = emAge[bk * MM + m] * (1.f - al[i]);
    }
}

// ---------------- launcher --------------------------------------------------------------
extern "C" void kernel_launch(void *const *d_in, const int *in_sizes, int n_in,
                              void *d_out, int out_size) {
    const float *seed     = (const float *)d_in[0];
    const float *wcand    = (const float *)d_in[1];
    const float *surprise = (const float *)d_in[2];
    const float *gem      = (const float *)d_in[3];
    const float *emK      = (const float *)d_in[4];
    const float *emV      = (const float *)d_in[5];
    const float *emS      = (const float *)d_in[6];
    const float *emAge    = (const float *)d_in[7];
    const float *w1       = (const float *)d_in[8];
    const float *w2       = (const float *)d_in[9];
    const float *gb       = (const float *)d_in[10];
    const float *rtau     = (const float *)d_in[11];
    const float *rtauw    = (const float *)d_in[12];
    float *out = (float *)d_out;

    cudaFuncSetAttribute(scores_mma_kernel<0>,
                         cudaFuncAttributeMaxDynamicSharedMemorySize, SC_BYTES);
    cudaFuncSetAttribute(scores_mma_kernel<1>,
                         cudaFuncAttributeMaxDynamicSharedMemorySize, SC_BYTES);
    cudaFuncSetAttribute(av_mma_kernel<0>,
                         cudaFuncAttributeMaxDynamicSharedMemorySize, AV_BYTES);
    cudaFuncSetAttribute(av_mma_kernel<1>,
                         cudaFuncAttributeMaxDynamicSharedMemorySize, AV_BYTES);
    cudaFuncSetAttribute(av_mma_kernel<2>,
                         cudaFuncAttributeMaxDynamicSharedMemorySize, AV_BYTES);
    cudaFuncSetAttribute(updkv_mma_kernel,
                         cudaFuncAttributeMaxDynamicSharedMemorySize, UK_BYTES);

    dim3 gS(16, 64), gA(8, 64), gU(8, 64);
    dim3 gT(16, 4, 64), bT(32, 8);

    transpose_v_kernel<<<gT, bT>>>(emV);
    init_y_kernel<<<8192, 256>>>(seed);
    wnorm_kernel<<<8192, 128>>>(wcand, surprise);

    scores_mma_kernel<0><<<gS, 512, SC_BYTES>>>(emK, emS, rtau, rtauw);
    av_mma_kernel<0><<<gA, 256, AV_BYTES>>>(w1, w2, gb, seed, wcand, out);
    scores_mma_kernel<0><<<gS, 512, SC_BYTES>>>(emK, emS, rtau, rtauw);
    av_mma_kernel<1><<<gA, 256, AV_BYTES>>>(w1, w2, gb, seed, wcand, out);

    scores_mma_kernel<1><<<gS, 512, SC_BYTES>>>(emK, emS, rtau, rtauw);
    av_mma_kernel<2><<<gA, 256, AV_BYTES>>>(w1, w2, gb, seed, wcand, out);

    swr_kernel<<<dim3(64, 4), 256>>>();
    updkv_mma_kernel<<<gU, 256, UK_BYTES>>>(wcand);
    final_kernel<<<64, 256>>>(emK, emV, emS, emAge, gem, out);
}